// round 13
// baseline (speedup 1.0000x reference)
#include <cuda_runtime.h>
#include <cuda_bf16.h>
#include <cstdint>

// ---------------- problem constants (fixed by the dataset) ----------------
#define NMAX 50000
#define EMAX 600000
#define DD   128
#define GMAX 128
#define PADK 136                        // bf16 per row (pad 8): conflict-free frags
#define NT   ((NMAX + 127) / 128)       // 391 tiles max

// ---------------- scratch (device globals; no allocation allowed) ---------
__device__ __align__(16) float g_h[NMAX * DD];
__device__ int g_cnt[NMAX];                   // zeroed by k_scan after use
__device__ int g_rowptr[NMAX + 1];
__device__ int g_cursor[NMAX];
__device__ int g_srcs[EMAX];
__device__ unsigned long long g_comb[128];    // lookback state; zeroed by k_count_init
// agg output, pre-converted bf16 hi/lo, tile-major PADK layout (mlp2's exact smem image)
__device__ __align__(16) __nv_bfloat16 g_aggh[NT * 128 * PADK];
__device__ __align__(16) __nv_bfloat16 g_aggl[NT * 128 * PADK];
// pre-transposed, bf16-split weights: [2L][n*128+k]  (B[n][k] = W[k][n])
__device__ __align__(16) __nv_bfloat16 g_wh[8 * DD * DD];
__device__ __align__(16) __nv_bfloat16 g_wl[8 * DD * DD];

__device__ __forceinline__ uint32_t pkbf(__nv_bfloat16 a, __nv_bfloat16 b) {
    return ((uint32_t)__bfloat16_as_ushort(b) << 16) | (uint32_t)__bfloat16_as_ushort(a);
}
__device__ __forceinline__ uint32_t hi2(float x, float y) {
    return pkbf(__float2bfloat16(x), __float2bfloat16(y));
}
__device__ __forceinline__ uint32_t lo2(float x, float y) {
    __nv_bfloat16 hx = __float2bfloat16(x), hy = __float2bfloat16(y);
    return pkbf(__float2bfloat16(x - __bfloat162float(hx)),
                __float2bfloat16(y - __bfloat162float(hy)));
}
__device__ __forceinline__ uint32_t smem_u32(const void* p) {
    uint32_t a;
    asm("{ .reg .u64 t; cvta.to.shared.u64 t, %1; cvt.u32.u64 %0, t; }"
        : "=r"(a) : "l"(p));
    return a;
}
__device__ __forceinline__ void cpa16(uint32_t s, const void* g) {
    asm volatile("cp.async.cg.shared.global [%0], [%1], 16;" :: "r"(s), "l"(g));
}
#define CP_COMMIT() asm volatile("cp.async.commit_group;" ::: "memory")
#define CP_WAIT0()  asm volatile("cp.async.wait_group 0;" ::: "memory")

// portable tensor-core mma (PTX ISA, sm_80+; works on bare sm_103 target)
__device__ __forceinline__ void mma16816(float* c, const uint32_t* a, const uint32_t* b) {
    asm volatile(
        "mma.sync.aligned.m16n8k16.row.col.f32.bf16.bf16.f32 "
        "{%0,%1,%2,%3}, {%4,%5,%6,%7}, {%8,%9}, {%0,%1,%2,%3};"
        : "+f"(c[0]), "+f"(c[1]), "+f"(c[2]), "+f"(c[3])
        : "r"(a[0]), "r"(a[1]), "r"(a[2]), "r"(a[3]), "r"(b[0]), "r"(b[1]));
}

// ---------------- kernels ----------------------------------------------------

// fused: [0,EB) degree histogram (4 edges/thr) + zero pooled/g_comb
//        [EB,EB+NBi) embedding init | rest: weight transpose + bf16 split
__global__ void k_count_init(const int* __restrict__ edge_index,
                             const int* __restrict__ feat_id,
                             const int* __restrict__ indeg,
                             const float* __restrict__ rwse,
                             const float* __restrict__ value_W,
                             const float* __restrict__ value_b,
                             const float* __restrict__ rwse_W,
                             const float* __restrict__ rwse_b,
                             const float* __restrict__ deg_emb,
                             const float* __restrict__ W1,
                             const float* __restrict__ W2,
                             float* __restrict__ pooled, int GD,
                             int N, int E, int RWSE, int DEGM1, int EB, int NBi) {
    if (blockIdx.x < EB) {
        int gi = blockIdx.x * 256 + threadIdx.x;
        if (gi < GD) pooled[gi] = 0.0f;                        // zero graph output
        if (blockIdx.x == 0 && threadIdx.x < 128) g_comb[threadIdx.x] = 0ull;
        const int* dst = edge_index + E;
        int e0 = blockIdx.x * 1024 + threadIdx.x;
#pragma unroll
        for (int k = 0; k < 4; k++) {                          // 4 indep atomic chains
            int e = e0 + k * 256;
            if (e < E) atomicAdd(&g_cnt[dst[e]], 1);
        }
        return;
    }
    if (blockIdx.x >= EB + NBi) {
        // ---- weight transpose + bf16 hi/lo split ----
        int m = blockIdx.x - (EB + NBi);     // 0..2L-1
        int l = m >> 1;
        const float* W = (m & 1) ? (W2 + l * DD * DD) : (W1 + l * DD * DD);
        __shared__ float t[32][33];
        int tx = threadIdx.x & 31, ty8 = threadIdx.x >> 5;  // 32 x 8
        for (int tile = 0; tile < 16; tile++) {
            int tr = tile >> 2, tc = tile & 3;
#pragma unroll
            for (int yy = 0; yy < 4; yy++) {
                int y = yy * 8 + ty8;
                t[y][tx] = W[(tr * 32 + y) * DD + tc * 32 + tx];
            }
            __syncthreads();
#pragma unroll
            for (int yy = 0; yy < 4; yy++) {
                int y = yy * 8 + ty8;
                int n = tc * 32 + y, k = tr * 32 + tx;
                float a = t[tx][y];              // = W[k][n]
                __nv_bfloat16 h = __float2bfloat16(a);
                __nv_bfloat16 lo = __float2bfloat16(a - __bfloat162float(h));
                g_wh[m * (DD * DD) + n * DD + k] = h;
                g_wl[m * (DD * DD) + n * DD + k] = lo;
            }
            __syncthreads();
        }
        return;
    }
    // ---- init h ----
    __shared__ float sRW[16 * DD];
    __shared__ float sVB[DD];
    __shared__ float sRB[DD];
    int tid = threadIdx.x;
    for (int i = tid; i < RWSE * DD; i += 256) sRW[i] = rwse_W[i];
    if (tid < DD) { sVB[tid] = value_b[tid]; sRB[tid] = rwse_b[tid]; }
    __syncthreads();

    int n = (blockIdx.x - EB) * 8 + (tid >> 5);
    if (n >= N) return;
    int lane = tid & 31;
    int c = lane * 4;

    int fid = feat_id[n] % 128;
    int dg = indeg[n];
    dg = dg < 0 ? 0 : (dg > DEGM1 ? DEGM1 : dg);

    float4 acc = *(const float4*)(value_W + fid * DD + c);
    float4 de  = *(const float4*)(deg_emb + dg * DD + c);
    acc.x += sVB[c]     + sRB[c]     + de.x;
    acc.y += sVB[c + 1] + sRB[c + 1] + de.y;
    acc.z += sVB[c + 2] + sRB[c + 2] + de.z;
    acc.w += sVB[c + 3] + sRB[c + 3] + de.w;

    const float* rrow = rwse + (long)n * RWSE;
#pragma unroll
    for (int k = 0; k < 16; k++) {
        float r = rrow[k];
        const float* w = sRW + k * DD + c;
        acc.x = fmaf(r, w[0], acc.x);
        acc.y = fmaf(r, w[1], acc.y);
        acc.z = fmaf(r, w[2], acc.z);
        acc.w = fmaf(r, w[3], acc.w);
    }
    *(float4*)(g_h + (long)n * DD + c) = acc;
}

// single-pass scan: block scan + decoupled lookback; self-cleans g_cnt
__global__ void k_scan(int N, int NB) {
    __shared__ int s[512];
    __shared__ int sexcl;
    int t = threadIdx.x, b = blockIdx.x;
    int i = b * 512 + t;
    int v = (i < N) ? g_cnt[i] : 0;
    s[t] = v;
    __syncthreads();
    for (int off = 1; off < 512; off <<= 1) {
        int x = (t >= off) ? s[t - off] : 0;
        __syncthreads();
        s[t] += x;
        __syncthreads();
    }
    if (t == 511) {
        int total = s[511];
        int excl = 0;
        if (b == 0) {
            *((volatile unsigned long long*)&g_comb[0]) =
                (2ull << 32) | (unsigned)total;
        } else {
            *((volatile unsigned long long*)&g_comb[b]) =
                (1ull << 32) | (unsigned)total;
            int j = b - 1;
            for (;;) {
                unsigned long long c;
                do { c = *((volatile unsigned long long*)&g_comb[j]); }
                while ((c >> 32) == 0);
                excl += (int)(unsigned)c;
                if ((c >> 32) == 2ull) break;
                j--;
            }
            *((volatile unsigned long long*)&g_comb[b]) =
                (2ull << 32) | (unsigned)(excl + total);
        }
        sexcl = excl;
        if (b == NB - 1) g_rowptr[N] = excl + total;
    }
    __syncthreads();
    int ex = sexcl;
    if (i < N) {
        int r = s[t] - v + ex;
        g_rowptr[i] = r;
        g_cursor[i] = r;
        g_cnt[i] = 0;          // self-clean for next kernel_launch call
    }
}

// CSR fill, 4 edges/thread (independent atomic chains hide ATOMG latency)
__global__ void k_fill(const int* __restrict__ src, const int* __restrict__ dst, int E) {
    int e0 = blockIdx.x * 1024 + threadIdx.x;
#pragma unroll
    for (int k = 0; k < 4; k++) {
        int e = e0 + k * 256;
        if (e < E) {
            int d = dst[e];
            int pos = atomicAdd(&g_cursor[d], 1);
            g_srcs[pos] = src[e];
        }
    }
}

// agg[n] = h[n] + sum_{CSR(n)} h[src]; 8 gathers in flight (deep MLP),
// dual accumulators; emit bf16 hi/lo in tile-major PADK layout.
__global__ void k_agg(int N) {
    int n = blockIdx.x * 8 + (threadIdx.x >> 5);
    if (n >= N) return;
    int lane = threadIdx.x & 31;
    const float4* hp = (const float4*)g_h;
    float4 acc = hp[n * 32 + lane];
    float4 acc2 = make_float4(0.f, 0.f, 0.f, 0.f);
    int beg = g_rowptr[n], end = g_rowptr[n + 1];
    int e = beg;
    for (; e + 7 < end; e += 8) {
        // load all 8 src indices first (uniform, 1-2 sectors), then 8 gathers in flight
        int s0 = g_srcs[e],     s1 = g_srcs[e + 1], s2 = g_srcs[e + 2], s3 = g_srcs[e + 3];
        int s4 = g_srcs[e + 4], s5 = g_srcs[e + 5], s6 = g_srcs[e + 6], s7 = g_srcs[e + 7];
        float4 v0 = hp[s0 * 32 + lane];
        float4 v1 = hp[s1 * 32 + lane];
        float4 v2 = hp[s2 * 32 + lane];
        float4 v3 = hp[s3 * 32 + lane];
        float4 v4 = hp[s4 * 32 + lane];
        float4 v5 = hp[s5 * 32 + lane];
        float4 v6 = hp[s6 * 32 + lane];
        float4 v7 = hp[s7 * 32 + lane];
        acc.x  += (v0.x + v1.x) + (v2.x + v3.x);
        acc.y  += (v0.y + v1.y) + (v2.y + v3.y);
        acc.z  += (v0.z + v1.z) + (v2.z + v3.z);
        acc.w  += (v0.w + v1.w) + (v2.w + v3.w);
        acc2.x += (v4.x + v5.x) + (v6.x + v7.x);
        acc2.y += (v4.y + v5.y) + (v6.y + v7.y);
        acc2.z += (v4.z + v5.z) + (v6.z + v7.z);
        acc2.w += (v4.w + v5.w) + (v6.w + v7.w);
    }
    if (e + 3 < end) {
        int s0 = g_srcs[e], s1 = g_srcs[e + 1], s2 = g_srcs[e + 2], s3 = g_srcs[e + 3];
        float4 v0 = hp[s0 * 32 + lane];
        float4 v1 = hp[s1 * 32 + lane];
        float4 v2 = hp[s2 * 32 + lane];
        float4 v3 = hp[s3 * 32 + lane];
        acc.x += (v0.x + v1.x) + (v2.x + v3.x);
        acc.y += (v0.y + v1.y) + (v2.y + v3.y);
        acc.z += (v0.z + v1.z) + (v2.z + v3.z);
        acc.w += (v0.w + v1.w) + (v2.w + v3.w);
        e += 4;
    }
    for (; e < end; e++) {
        float4 v0 = hp[g_srcs[e] * 32 + lane];
        acc.x += v0.x; acc.y += v0.y; acc.z += v0.z; acc.w += v0.w;
    }
    acc.x += acc2.x; acc.y += acc2.y; acc.z += acc2.z; acc.w += acc2.w;
    int base = (n >> 7) * (128 * PADK) + (n & 127) * PADK + lane * 4;
    uint2 wh, wl;
    wh.x = hi2(acc.x, acc.y); wh.y = hi2(acc.z, acc.w);
    wl.x = lo2(acc.x, acc.y); wl.y = lo2(acc.z, acc.w);
    *(uint2*)(g_aggh + base) = wh;
    *(uint2*)(g_aggl + base) = wl;
}

// ---------------- fused 2-GEMM MLP (tensor core, scalar-LDS frags: R10) -----
#define MATB (128 * PADK * 2)          // 34816 bytes per matrix
#define OFF_AH 2048
#define OFF_AL (OFF_AH + MATB)
#define OFF_B1H (OFF_AL + MATB)
#define OFF_B1L (OFF_B1H + MATB)
#define OFF_B2H (OFF_B1L + MATB)
#define OFF_B2L (OFF_B2H + MATB)
#define SMEM_MLP2 (OFF_B2L + MATB)     // 210944 bytes

__device__ __forceinline__ void gemm_tile(const __nv_bfloat16* sAH, const __nv_bfloat16* sAL,
                                          const __nv_bfloat16* sBH, const __nv_bfloat16* sBL,
                                          int wm, int wn, int tg, int tq, float (*c)[4]) {
#pragma unroll
    for (int i = 0; i < 8; i++) { c[i][0] = c[i][1] = c[i][2] = c[i][3] = 0.f; }
#pragma unroll
    for (int ks = 0; ks < 8; ks++) {
        int k0 = ks * 16 + tq * 2;
        uint32_t ah[2][4], al[2][4], bh[4][2], bl[4][2];
#pragma unroll
        for (int mi = 0; mi < 2; mi++) {
            int base = (wm * 32 + mi * 16 + tg) * PADK + k0;
            ah[mi][0] = *(const uint32_t*)(sAH + base);
            ah[mi][1] = *(const uint32_t*)(sAH + base + 8 * PADK);
            ah[mi][2] = *(const uint32_t*)(sAH + base + 8);
            ah[mi][3] = *(const uint32_t*)(sAH + base + 8 * PADK + 8);
            al[mi][0] = *(const uint32_t*)(sAL + base);
            al[mi][1] = *(const uint32_t*)(sAL + base + 8 * PADK);
            al[mi][2] = *(const uint32_t*)(sAL + base + 8);
            al[mi][3] = *(const uint32_t*)(sAL + base + 8 * PADK + 8);
        }
#pragma unroll
        for (int ni = 0; ni < 4; ni++) {
            int base = (wn * 32 + ni * 8 + tg) * PADK + k0;
            bh[ni][0] = *(const uint32_t*)(sBH + base);
            bh[ni][1] = *(const uint32_t*)(sBH + base + 8);
            bl[ni][0] = *(const uint32_t*)(sBL + base);
            bl[ni][1] = *(const uint32_t*)(sBL + base + 8);
        }
#pragma unroll
        for (int mi = 0; mi < 2; mi++) {
#pragma unroll
            for (int ni = 0; ni < 4; ni++) {
                float* cc = c[mi * 4 + ni];
                mma16816(cc, ah[mi], bh[ni]);
                mma16816(cc, al[mi], bh[ni]);
                mma16816(cc, ah[mi], bl[ni]);
            }
        }
    }
}

__global__ void __launch_bounds__(512, 1)
k_mlp2(float* __restrict__ out, int l,
       const float* __restrict__ b1,
       const float* __restrict__ gamma, const float* __restrict__ beta,
       const float* __restrict__ mean, const float* __restrict__ var,
       const float* __restrict__ b2,
       const int* __restrict__ batch, float* __restrict__ pooled,
       int N, int do_pool) {
    extern __shared__ char smc[];
    float* sm = (float*)smc;  // [0,128) sc  [128,256) sh  [256,384) b1
    __nv_bfloat16* sAH  = (__nv_bfloat16*)(smc + OFF_AH);
    __nv_bfloat16* sAL  = (__nv_bfloat16*)(smc + OFF_AL);
    __nv_bfloat16* sB1H = (__nv_bfloat16*)(smc + OFF_B1H);
    __nv_bfloat16* sB1L = (__nv_bfloat16*)(smc + OFF_B1L);
    __nv_bfloat16* sB2H = (__nv_bfloat16*)(smc + OFF_B2H);
    __nv_bfloat16* sB2L = (__nv_bfloat16*)(smc + OFF_B2L);
    int tid = threadIdx.x;
    uint32_t sb = smem_u32(smc);

    // header: BN folded into sc/sh, plus b1
    if (tid < 128) {
        float sc = gamma[tid] * rsqrtf(var[tid] + 1e-5f);
        sm[tid]       = sc;
        sm[128 + tid] = (b2[tid] - mean[tid]) * sc + beta[tid];
        sm[256 + tid] = b1[tid];
    }
    // B1/B2 load (once per launch)
    {
        const uint4* s1h = (const uint4*)(g_wh + (2 * l) * (DD * DD));
        const uint4* s1l = (const uint4*)(g_wl + (2 * l) * (DD * DD));
        const uint4* s2h = (const uint4*)(g_wh + (2 * l + 1) * (DD * DD));
        const uint4* s2l = (const uint4*)(g_wl + (2 * l + 1) * (DD * DD));
        for (int i = tid; i < 2048; i += 512) {
            int n = i >> 4, k8 = (i & 15) << 3;
            int off = n * PADK + k8;
            *(uint4*)(sB1H + off) = s1h[i];
            *(uint4*)(sB1L + off) = s1l[i];
            *(uint4*)(sB2H + off) = s2h[i];
            *(uint4*)(sB2L + off) = s2l[i];
        }
    }

    int w = tid >> 5, lane = tid & 31;
    int wm = w & 3, wn = w >> 2;
    int tg = lane >> 2, tq = lane & 3;

    int ntiles = (N + 127) >> 7;
    for (int tile = blockIdx.x; tile < ntiles; tile += gridDim.x) {
        int n0 = tile << 7;
        __syncthreads();   // prev tile's A reads done; B/header visible (1st iter)

        // ---- stage A tile: flat cp.async copy of pre-converted hi/lo ----
        {
            const char* srcH = (const char*)g_aggh + (size_t)tile * MATB;
            const char* srcL = (const char*)g_aggl + (size_t)tile * MATB;
            for (int i = tid; i < MATB / 16; i += 512) {   // 2176 chunks
                cpa16(sb + OFF_AH + i * 16, srcH + i * 16);
                cpa16(sb + OFF_AL + i * 16, srcL + i * 16);
            }
            CP_COMMIT();
            CP_WAIT0();
        }
        __syncthreads();

        // ---- GEMM1: t = relu(agg @ W1 + b1) ----
        float c[8][4];
        gemm_tile(sAH, sAL, sB1H, sB1L, wm, wn, tg, tq, c);
        __syncthreads();   // all A reads done before overwrite with t
#pragma unroll
        for (int mi = 0; mi < 2; mi++) {
#pragma unroll
            for (int ni = 0; ni < 4; ni++) {
                int colc = wn * 32 + ni * 8 + tq * 2;
                float bb0 = sm[256 + colc], bb1 = sm[256 + colc + 1];
                const float* cc = c[mi * 4 + ni];
                int r0 = wm * 32 + mi * 16 + tg;
                float t0 = fmaxf(cc[0] + bb0, 0.f), t1 = fmaxf(cc[1] + bb1, 0.f);
                float t2 = fmaxf(cc[2] + bb0, 0.f), t3 = fmaxf(cc[3] + bb1, 0.f);
                *(uint32_t*)(sAH + r0 * PADK + colc)       = hi2(t0, t1);
                *(uint32_t*)(sAL + r0 * PADK + colc)       = lo2(t0, t1);
                *(uint32_t*)(sAH + (r0 + 8) * PADK + colc) = hi2(t2, t3);
                *(uint32_t*)(sAL + (r0 + 8) * PADK + colc) = lo2(t2, t3);
            }
        }
        __syncthreads();

        // ---- GEMM2: h = relu(BN(t @ W2 + b2)) (+pool) ----
        gemm_tile(sAH, sAL, sB2H, sB2L, wm, wn, tg, tq, c);
#pragma unroll
        for (int mi = 0; mi < 2; mi++) {
#pragma unroll
            for (int ni = 0; ni < 4; ni++) {
                int colc = wn * 32 + ni * 8 + tq * 2;
                float sc0 = sm[colc], sc1 = sm[colc + 1];
                float sh0 = sm[128 + colc], sh1 = sm[128 + colc + 1];
                const float* cc = c[mi * 4 + ni];
                int r0 = n0 + wm * 32 + mi * 16 + tg;
                int r1 = r0 + 8;
                if (r0 < N) {
                    float2 o;
                    o.x = fmaxf(fmaf(cc[0], sc0, sh0), 0.f);
                    o.y = fmaxf(fmaf(cc[1], sc1, sh1), 0.f);
                    *(float2*)(out + (long)r0 * DD + colc) = o;
                    if (do_pool) {
                        int g = batch[r0];
                        atomicAdd(pooled + g * DD + colc, o.x);
                        atomicAdd(pooled + g * DD + colc + 1, o.y);
                    }
                }
                if (r1 < N) {
                    float2 o;
                    o.x = fmaxf(fmaf(cc[2], sc0, sh0), 0.f);
                    o.y = fmaxf(fmaf(cc[3], sc1, sh1), 0.f);
                    *(float2*)(out + (long)r1 * DD + colc) = o;
                    if (do_pool) {
                        int g = batch[r1];
                        atomicAdd(pooled + g * DD + colc, o.x);
                        atomicAdd(pooled + g * DD + colc + 1, o.y);
                    }
                }
            }
        }
    }
}

// mean divide; per-graph count via binary search on the SORTED batch array
__global__ void k_pooldiv(float* pooled, const int* __restrict__ batch, int N) {
    __shared__ int scount;
    int g = blockIdx.x;
    if (threadIdx.x == 0) {
        int lo = 0, hi = N;
        while (lo < hi) { int m = (lo + hi) >> 1; if (batch[m] < g) lo = m + 1; else hi = m; }
        int lo2_ = lo, hi2_ = N;
        while (lo2_ < hi2_) { int m = (lo2_ + hi2_) >> 1; if (batch[m] <= g) lo2_ = m + 1; else hi2_ = m; }
        scount = lo2_ - lo;
    }
    __syncthreads();
    float cnt = fmaxf((float)scount, 1.0f);
    pooled[g * DD + threadIdx.x] /= cnt;
}

// ---------------- launcher --------------------------------------------------
extern "C" void kernel_launch(void* const* d_in, const int* in_sizes, int n_in,
                              void* d_out, int out_size) {
    const int*   feat_id = (const int*)d_in[0];
    const int*   edge_index = (const int*)d_in[1];
    const int*   batch = (const int*)d_in[2];
    const float* rwse = (const float*)d_in[3];
    const int*   indeg = (const int*)d_in[4];
    const float* value_W = (const float*)d_in[5];
    const float* value_b = (const float*)d_in[6];
    const float* rwse_W = (const float*)d_in[7];
    const float* rwse_b = (const float*)d_in[8];
    const float* deg_emb = (const float*)d_in[9];
    const float* W1 = (const float*)d_in[10];
    const float* b1 = (const float*)d_in[11];
    const float* W2 = (const float*)d_in[12];
    const float* b2 = (const float*)d_in[13];
    const float* gamma = (const float*)d_in[14];
    const float* beta = (const float*)d_in[15];
    const float* mean = (const float*)d_in[16];
    const float* var = (const float*)d_in[17];

    int N = in_sizes[0];
    int E = in_sizes[1] / 2;
    int RWSE = in_sizes[3] / N;
    int DEG = in_sizes[9] / DD;
    int L = in_sizes[10] / (DD * DD);

    // resolve device addresses of __device__ globals (host symbol != device ptr)
    float* d_gh = 0;
    cudaGetSymbolAddress((void**)&d_gh, g_h);

    long outRows = (long)out_size / DD;
    bool both = (outRows > (long)N);
    int G = both ? (int)(outRows - N) : (int)outRows;

    float* pooled = (float*)d_out;
    float* hout = both ? (pooled + (long)G * DD) : d_gh;

    cudaFuncSetAttribute(k_mlp2, cudaFuncAttributeMaxDynamicSharedMemorySize, SMEM_MLP2);

    // (1) degree histogram + zero(pooled,g_comb) + embedding init + weight prep
    int EB = (E + 1023) / 1024;
    int NBi = (N + 7) / 8;
    k_count_init<<<EB + NBi + 2 * L, 256>>>(edge_index, feat_id, indeg, rwse,
                                            value_W, value_b, rwse_W, rwse_b, deg_emb,
                                            W1, W2, pooled, G * DD,
                                            N, E, RWSE, DEG - 1, EB, NBi);

    // (2) single-pass rowptr scan (decoupled lookback; self-cleans g_cnt)
    int NB = (N + 511) / 512;
    k_scan<<<NB, 512>>>(N, NB);

    // (3) CSR fill (4 edges/thread)
    k_fill<<<(E + 1023) / 1024, 256>>>(edge_index, edge_index + E, E);

    // (4..) GIN layers: deep-pipelined gather (launch #4 = profiled) + 2-GEMM MLP
    int ntiles = (N + 127) / 128;
    int lgrid = ntiles < 148 ? ntiles : 148;
    for (int l = 0; l < L; l++) {
        bool last = (l == L - 1);
        k_agg<<<(N + 7) / 8, 256>>>(N);
        k_mlp2<<<lgrid, 512, SMEM_MLP2>>>(last ? hout : d_gh, l,
                                          b1 + l * DD,
                                          gamma + l * DD, beta + l * DD,
                                          mean + l * DD, var + l * DD, b2 + l * DD,
                                          batch, pooled, N, last ? 1 : 0);
    }

    // final mean divide (count via binary search on sorted batch)
    k_pooldiv<<<G, 128>>>(pooled, batch, N);
}

// round 14
// speedup vs baseline: 1.1621x; 1.1621x over previous
#include <cuda_runtime.h>
#include <cuda_fp16.h>
#include <cstdint>

// ---------------- problem constants (fixed by the dataset) ----------------
#define NMAX 50000
#define EMAX 600000
#define DD   128
#define GMAX 128
#define PADK 136                        // fp16 per row (pad 8): conflict-free frags
#define NT   ((NMAX + 127) / 128)       // 391 tiles max

// ---------------- scratch (device globals; no allocation allowed) ---------
__device__ __align__(16) float g_h[NMAX * DD];
__device__ int g_cnt[NMAX];                   // zeroed by k_scan after use
__device__ int g_rowptr[NMAX + 1];
__device__ int g_cursor[NMAX];
__device__ int g_srcs[EMAX];
__device__ unsigned long long g_comb[128];    // lookback state; zeroed by k_count_init
// agg output, pre-converted fp16 hi/lo, tile-major PADK layout (mlp2's smem image)
__device__ __align__(16) __half g_aggh[NT * 128 * PADK];
__device__ __align__(16) __half g_aggl[NT * 128 * PADK];
// pre-transposed fp16 weights (hi only): [2L][n*128+k]  (B[n][k] = W[k][n])
__device__ __align__(16) __half g_wh[8 * DD * DD];

__device__ __forceinline__ uint32_t fh2(float x, float y) {
    __half2 h = __floats2half2_rn(x, y);
    return *(uint32_t*)&h;
}
__device__ __forceinline__ uint32_t fl2(float x, float y) {
    float rx = x - __half2float(__float2half_rn(x));
    float ry = y - __half2float(__float2half_rn(y));
    return fh2(rx, ry);
}
__device__ __forceinline__ uint32_t smem_u32(const void* p) {
    uint32_t a;
    asm("{ .reg .u64 t; cvta.to.shared.u64 t, %1; cvt.u32.u64 %0, t; }"
        : "=r"(a) : "l"(p));
    return a;
}
__device__ __forceinline__ void cpa16(uint32_t s, const void* g) {
    asm volatile("cp.async.cg.shared.global [%0], [%1], 16;" :: "r"(s), "l"(g));
}
#define CP_COMMIT() asm volatile("cp.async.commit_group;" ::: "memory")
#define CP_WAIT1()  asm volatile("cp.async.wait_group 1;" ::: "memory")

// portable tensor-core mma fp16 (PTX ISA, sm_70+; works on bare sm_103 target)
__device__ __forceinline__ void mma16816(float* c, const uint32_t* a, const uint32_t* b) {
    asm volatile(
        "mma.sync.aligned.m16n8k16.row.col.f32.f16.f16.f32 "
        "{%0,%1,%2,%3}, {%4,%5,%6,%7}, {%8,%9}, {%0,%1,%2,%3};"
        : "+f"(c[0]), "+f"(c[1]), "+f"(c[2]), "+f"(c[3])
        : "r"(a[0]), "r"(a[1]), "r"(a[2]), "r"(a[3]), "r"(b[0]), "r"(b[1]));
}

// ---------------- kernels ----------------------------------------------------

// fused: [0,EB) degree histogram (4 edges/thr) + zero pooled/g_comb
//        [EB,EB+NBi) embedding init | rest: weight transpose + fp16 quantize
__global__ void k_count_init(const int* __restrict__ edge_index,
                             const int* __restrict__ feat_id,
                             const int* __restrict__ indeg,
                             const float* __restrict__ rwse,
                             const float* __restrict__ value_W,
                             const float* __restrict__ value_b,
                             const float* __restrict__ rwse_W,
                             const float* __restrict__ rwse_b,
                             const float* __restrict__ deg_emb,
                             const float* __restrict__ W1,
                             const float* __restrict__ W2,
                             float* __restrict__ pooled, int GD,
                             int N, int E, int RWSE, int DEGM1, int EB, int NBi) {
    if (blockIdx.x < EB) {
        int gi = blockIdx.x * 256 + threadIdx.x;
        if (gi < GD) pooled[gi] = 0.0f;                        // zero graph output
        if (blockIdx.x == 0 && threadIdx.x < 128) g_comb[threadIdx.x] = 0ull;
        const int* dst = edge_index + E;
        int e0 = blockIdx.x * 1024 + threadIdx.x;
#pragma unroll
        for (int k = 0; k < 4; k++) {                          // 4 indep atomic chains
            int e = e0 + k * 256;
            if (e < E) atomicAdd(&g_cnt[dst[e]], 1);
        }
        return;
    }
    if (blockIdx.x >= EB + NBi) {
        // ---- weight transpose + fp16 quantize (hi only) ----
        int m = blockIdx.x - (EB + NBi);     // 0..2L-1
        int l = m >> 1;
        const float* W = (m & 1) ? (W2 + l * DD * DD) : (W1 + l * DD * DD);
        __shared__ float t[32][33];
        int tx = threadIdx.x & 31, ty8 = threadIdx.x >> 5;  // 32 x 8
        for (int tile = 0; tile < 16; tile++) {
            int tr = tile >> 2, tc = tile & 3;
#pragma unroll
            for (int yy = 0; yy < 4; yy++) {
                int y = yy * 8 + ty8;
                t[y][tx] = W[(tr * 32 + y) * DD + tc * 32 + tx];
            }
            __syncthreads();
#pragma unroll
            for (int yy = 0; yy < 4; yy++) {
                int y = yy * 8 + ty8;
                int n = tc * 32 + y, k = tr * 32 + tx;
                g_wh[m * (DD * DD) + n * DD + k] = __float2half_rn(t[tx][y]);
            }
            __syncthreads();
        }
        return;
    }
    // ---- init h ----
    __shared__ float sRW[16 * DD];
    __shared__ float sVB[DD];
    __shared__ float sRB[DD];
    int tid = threadIdx.x;
    for (int i = tid; i < RWSE * DD; i += 256) sRW[i] = rwse_W[i];
    if (tid < DD) { sVB[tid] = value_b[tid]; sRB[tid] = rwse_b[tid]; }
    __syncthreads();

    int n = (blockIdx.x - EB) * 8 + (tid >> 5);
    if (n >= N) return;
    int lane = tid & 31;
    int c = lane * 4;

    int fid = feat_id[n] % 128;
    int dg = indeg[n];
    dg = dg < 0 ? 0 : (dg > DEGM1 ? DEGM1 : dg);

    float4 acc = *(const float4*)(value_W + fid * DD + c);
    float4 de  = *(const float4*)(deg_emb + dg * DD + c);
    acc.x += sVB[c]     + sRB[c]     + de.x;
    acc.y += sVB[c + 1] + sRB[c + 1] + de.y;
    acc.z += sVB[c + 2] + sRB[c + 2] + de.z;
    acc.w += sVB[c + 3] + sRB[c + 3] + de.w;

    const float* rrow = rwse + (long)n * RWSE;
#pragma unroll
    for (int k = 0; k < 16; k++) {
        float r = rrow[k];
        const float* w = sRW + k * DD + c;
        acc.x = fmaf(r, w[0], acc.x);
        acc.y = fmaf(r, w[1], acc.y);
        acc.z = fmaf(r, w[2], acc.z);
        acc.w = fmaf(r, w[3], acc.w);
    }
    *(float4*)(g_h + (long)n * DD + c) = acc;
}

// single-pass scan: block scan + decoupled lookback; self-cleans g_cnt
__global__ void k_scan(int N, int NB) {
    __shared__ int s[512];
    __shared__ int sexcl;
    int t = threadIdx.x, b = blockIdx.x;
    int i = b * 512 + t;
    int v = (i < N) ? g_cnt[i] : 0;
    s[t] = v;
    __syncthreads();
    for (int off = 1; off < 512; off <<= 1) {
        int x = (t >= off) ? s[t - off] : 0;
        __syncthreads();
        s[t] += x;
        __syncthreads();
    }
    if (t == 511) {
        int total = s[511];
        int excl = 0;
        if (b == 0) {
            *((volatile unsigned long long*)&g_comb[0]) =
                (2ull << 32) | (unsigned)total;
        } else {
            *((volatile unsigned long long*)&g_comb[b]) =
                (1ull << 32) | (unsigned)total;
            int j = b - 1;
            for (;;) {
                unsigned long long c;
                do { c = *((volatile unsigned long long*)&g_comb[j]); }
                while ((c >> 32) == 0);
                excl += (int)(unsigned)c;
                if ((c >> 32) == 2ull) break;
                j--;
            }
            *((volatile unsigned long long*)&g_comb[b]) =
                (2ull << 32) | (unsigned)(excl + total);
        }
        sexcl = excl;
        if (b == NB - 1) g_rowptr[N] = excl + total;
    }
    __syncthreads();
    int ex = sexcl;
    if (i < N) {
        int r = s[t] - v + ex;
        g_rowptr[i] = r;
        g_cursor[i] = r;
        g_cnt[i] = 0;          // self-clean for next kernel_launch call
    }
}

// CSR fill, 4 edges/thread (independent atomic chains hide ATOMG latency)
__global__ void k_fill(const int* __restrict__ src, const int* __restrict__ dst, int E) {
    int e0 = blockIdx.x * 1024 + threadIdx.x;
#pragma unroll
    for (int k = 0; k < 4; k++) {
        int e = e0 + k * 256;
        if (e < E) {
            int d = dst[e];
            int pos = atomicAdd(&g_cursor[d], 1);
            g_srcs[pos] = src[e];
        }
    }
}

// agg[n] = h[n] + sum_{CSR(n)} h[src] (R10 loop — at LTS cap); emit fp16 hi/lo
__global__ void k_agg(int N) {
    int n = blockIdx.x * 8 + (threadIdx.x >> 5);
    if (n >= N) return;
    int lane = threadIdx.x & 31;
    const float4* hp = (const float4*)g_h;
    float4 acc = hp[n * 32 + lane];
    int beg = g_rowptr[n], end = g_rowptr[n + 1];
    int e = beg;
    for (; e + 3 < end; e += 4) {
        int s0 = g_srcs[e] * 32 + lane, s1 = g_srcs[e + 1] * 32 + lane;
        int s2 = g_srcs[e + 2] * 32 + lane, s3 = g_srcs[e + 3] * 32 + lane;
        float4 v0 = hp[s0];
        float4 v1 = hp[s1];
        float4 v2 = hp[s2];
        float4 v3 = hp[s3];
        acc.x += (v0.x + v1.x) + (v2.x + v3.x);
        acc.y += (v0.y + v1.y) + (v2.y + v3.y);
        acc.z += (v0.z + v1.z) + (v2.z + v3.z);
        acc.w += (v0.w + v1.w) + (v2.w + v3.w);
    }
    for (; e < end; e++) {
        float4 v0 = hp[g_srcs[e] * 32 + lane];
        acc.x += v0.x; acc.y += v0.y; acc.z += v0.z; acc.w += v0.w;
    }
    int base = (n >> 7) * (128 * PADK) + (n & 127) * PADK + lane * 4;
    uint2 wh, wl;
    wh.x = fh2(acc.x, acc.y); wh.y = fh2(acc.z, acc.w);
    wl.x = fl2(acc.x, acc.y); wl.y = fl2(acc.z, acc.w);
    *(uint2*)(g_aggh + base) = wh;
    *(uint2*)(g_aggl + base) = wl;
}

// ---------------- fused 2-GEMM MLP (fp16 2-term, double-buffered A) ---------
#define MATB  (128 * PADK * 2)          // 34816 bytes per matrix
#define ABUF  (2 * MATB)                // A hi+lo per buffer = 69632 bytes
#define OFF_A0 2048
#define OFF_A1 (OFF_A0 + ABUF)
#define OFF_B1H (OFF_A1 + ABUF)
#define OFF_B2H (OFF_B1H + MATB)
#define SMEM_MLP2 (OFF_B2H + MATB)      // 210944 bytes
#define NHALF (MATB / 2)                // halfs per matrix (17408)

// 2-term: D = Ah@Bh + Al@Bh  (A full precision, W quantized fp16)
__device__ __forceinline__ void gemm_tile(const __half* sA, const __half* sBH,
                                          int wm, int wn, int tg, int tq, float (*c)[4]) {
    const __half* sAH = sA;
    const __half* sAL = sA + NHALF;
#pragma unroll
    for (int i = 0; i < 8; i++) { c[i][0] = c[i][1] = c[i][2] = c[i][3] = 0.f; }
#pragma unroll
    for (int ks = 0; ks < 8; ks++) {
        int k0 = ks * 16 + tq * 2;
        uint32_t ah[2][4], al[2][4], bh[4][2];
#pragma unroll
        for (int mi = 0; mi < 2; mi++) {
            int base = (wm * 32 + mi * 16 + tg) * PADK + k0;
            ah[mi][0] = *(const uint32_t*)(sAH + base);
            ah[mi][1] = *(const uint32_t*)(sAH + base + 8 * PADK);
            ah[mi][2] = *(const uint32_t*)(sAH + base + 8);
            ah[mi][3] = *(const uint32_t*)(sAH + base + 8 * PADK + 8);
            al[mi][0] = *(const uint32_t*)(sAL + base);
            al[mi][1] = *(const uint32_t*)(sAL + base + 8 * PADK);
            al[mi][2] = *(const uint32_t*)(sAL + base + 8);
            al[mi][3] = *(const uint32_t*)(sAL + base + 8 * PADK + 8);
        }
#pragma unroll
        for (int ni = 0; ni < 4; ni++) {
            int base = (wn * 32 + ni * 8 + tg) * PADK + k0;
            bh[ni][0] = *(const uint32_t*)(sBH + base);
            bh[ni][1] = *(const uint32_t*)(sBH + base + 8);
        }
#pragma unroll
        for (int mi = 0; mi < 2; mi++) {
#pragma unroll
            for (int ni = 0; ni < 4; ni++) {
                float* cc = c[mi * 4 + ni];
                mma16816(cc, ah[mi], bh[ni]);
                mma16816(cc, al[mi], bh[ni]);
            }
        }
    }
}

__global__ void __launch_bounds__(512, 1)
k_mlp2(float* __restrict__ out, int l,
       const float* __restrict__ b1,
       const float* __restrict__ gamma, const float* __restrict__ beta,
       const float* __restrict__ mean, const float* __restrict__ var,
       const float* __restrict__ b2,
       const int* __restrict__ batch, float* __restrict__ pooled,
       int N, int do_pool) {
    extern __shared__ char smc[];
    float* sm = (float*)smc;  // [0,128) sc  [128,256) sh  [256,384) b1
    __half* sB1H = (__half*)(smc + OFF_B1H);
    __half* sB2H = (__half*)(smc + OFF_B2H);
    int tid = threadIdx.x;
    uint32_t sb = smem_u32(smc);

    // header: BN folded into sc/sh, plus b1
    if (tid < 128) {
        float sc = gamma[tid] * rsqrtf(var[tid] + 1e-5f);
        sm[tid]       = sc;
        sm[128 + tid] = (b2[tid] - mean[tid]) * sc + beta[tid];
        sm[256 + tid] = b1[tid];
    }
    // B1/B2 hi load (once per launch)
    {
        const uint4* s1h = (const uint4*)(g_wh + (2 * l) * (DD * DD));
        const uint4* s2h = (const uint4*)(g_wh + (2 * l + 1) * (DD * DD));
        for (int i = tid; i < 2048; i += 512) {
            int n = i >> 4, k8 = (i & 15) << 3;
            int off = n * PADK + k8;
            *(uint4*)(sB1H + off) = s1h[i];
            *(uint4*)(sB2H + off) = s2h[i];
        }
    }

    int w = tid >> 5, lane = tid & 31;
    int wm = w & 3, wn = w >> 2;
    int tg = lane >> 2, tq = lane & 3;

    int ntiles = (N + 127) >> 7;
    int stride = gridDim.x;

    // prime: prefetch first tile into buffer 0
    if (blockIdx.x < ntiles) {
        const char* srcH = (const char*)g_aggh + (size_t)blockIdx.x * MATB;
        const char* srcL = (const char*)g_aggl + (size_t)blockIdx.x * MATB;
        for (int i = tid; i < MATB / 16; i += 512) {
            cpa16(sb + OFF_A0 + i * 16, srcH + i * 16);
            cpa16(sb + OFF_A0 + MATB + i * 16, srcL + i * 16);
        }
    }
    CP_COMMIT();

    int pb = 0;
    for (int tile = blockIdx.x; tile < ntiles; tile += stride) {
        __syncthreads();   // prev iter's reads of the other buffer done; B visible

        // prefetch next tile into the other buffer (clamped when out of range)
        {
            int nxt = tile + stride;
            int pre = (nxt < ntiles) ? nxt : tile;
            uint32_t dst = sb + (pb ? OFF_A0 : OFF_A1);
            const char* srcH = (const char*)g_aggh + (size_t)pre * MATB;
            const char* srcL = (const char*)g_aggl + (size_t)pre * MATB;
            for (int i = tid; i < MATB / 16; i += 512) {
                cpa16(dst + i * 16, srcH + i * 16);
                cpa16(dst + MATB + i * 16, srcL + i * 16);
            }
            CP_COMMIT();
        }
        CP_WAIT1();        // current buffer's prefetch complete
        __syncthreads();

        __half* sA = (__half*)(smc + (pb ? OFF_A1 : OFF_A0));
        int n0 = tile << 7;

        // ---- GEMM1: t = relu(agg @ W1 + b1) ----
        float c[8][4];
        gemm_tile(sA, sB1H, wm, wn, tg, tq, c);
        __syncthreads();   // all A reads done before overwrite with t
#pragma unroll
        for (int mi = 0; mi < 2; mi++) {
#pragma unroll
            for (int ni = 0; ni < 4; ni++) {
                int colc = wn * 32 + ni * 8 + tq * 2;
                float bb0 = sm[256 + colc], bb1 = sm[256 + colc + 1];
                const float* cc = c[mi * 4 + ni];
                int r0 = wm * 32 + mi * 16 + tg;
                float t0 = fmaxf(cc[0] + bb0, 0.f), t1 = fmaxf(cc[1] + bb1, 0.f);
                float t2 = fmaxf(cc[2] + bb0, 0.f), t3 = fmaxf(cc[3] + bb1, 0.f);
                *(uint32_t*)(sA + r0 * PADK + colc)                 = fh2(t0, t1);
                *(uint32_t*)(sA + NHALF + r0 * PADK + colc)         = fl2(t0, t1);
                *(uint32_t*)(sA + (r0 + 8) * PADK + colc)           = fh2(t2, t3);
                *(uint32_t*)(sA + NHALF + (r0 + 8) * PADK + colc)   = fl2(t2, t3);
            }
        }
        __syncthreads();

        // ---- GEMM2: h = relu(BN(t @ W2 + b2)) (+pool) ----
        gemm_tile(sA, sB2H, wm, wn, tg, tq, c);
#pragma unroll
        for (int mi = 0; mi < 2; mi++) {
#pragma unroll
            for (int ni = 0; ni < 4; ni++) {
                int colc = wn * 32 + ni * 8 + tq * 2;
                float sc0 = sm[colc], sc1 = sm[colc + 1];
                float sh0 = sm[128 + colc], sh1 = sm[128 + colc + 1];
                const float* cc = c[mi * 4 + ni];
                int r0 = n0 + wm * 32 + mi * 16 + tg;
                int r1 = r0 + 8;
                if (r0 < N) {
                    float2 o;
                    o.x = fmaxf(fmaf(cc[0], sc0, sh0), 0.f);
                    o.y = fmaxf(fmaf(cc[1], sc1, sh1), 0.f);
                    *(float2*)(out + (long)r0 * DD + colc) = o;
                    if (do_pool) {
                        int g = batch[r0];
                        atomicAdd(pooled + g * DD + colc, o.x);
                        atomicAdd(pooled + g * DD + colc + 1, o.y);
                    }
                }
                if (r1 < N) {
                    float2 o;
                    o.x = fmaxf(fmaf(cc[2], sc0, sh0), 0.f);
                    o.y = fmaxf(fmaf(cc[3], sc1, sh1), 0.f);
                    *(float2*)(out + (long)r1 * DD + colc) = o;
                    if (do_pool) {
                        int g = batch[r1];
                        atomicAdd(pooled + g * DD + colc, o.x);
                        atomicAdd(pooled + g * DD + colc + 1, o.y);
                    }
                }
            }
        }
        pb ^= 1;
    }
}

// mean divide; per-graph count via binary search on the SORTED batch array
__global__ void k_pooldiv(float* pooled, const int* __restrict__ batch, int N) {
    __shared__ int scount;
    int g = blockIdx.x;
    if (threadIdx.x == 0) {
        int lo = 0, hi = N;
        while (lo < hi) { int m = (lo + hi) >> 1; if (batch[m] < g) lo = m + 1; else hi = m; }
        int lo2_ = lo, hi2_ = N;
        while (lo2_ < hi2_) { int m = (lo2_ + hi2_) >> 1; if (batch[m] <= g) lo2_ = m + 1; else hi2_ = m; }
        scount = lo2_ - lo;
    }
    __syncthreads();
    float cnt = fmaxf((float)scount, 1.0f);
    pooled[g * DD + threadIdx.x] /= cnt;
}

// ---------------- launcher --------------------------------------------------
extern "C" void kernel_launch(void* const* d_in, const int* in_sizes, int n_in,
                              void* d_out, int out_size) {
    const int*   feat_id = (const int*)d_in[0];
    const int*   edge_index = (const int*)d_in[1];
    const int*   batch = (const int*)d_in[2];
    const float* rwse = (const float*)d_in[3];
    const int*   indeg = (const int*)d_in[4];
    const float* value_W = (const float*)d_in[5];
    const float* value_b = (const float*)d_in[6];
    const float* rwse_W = (const float*)d_in[7];
    const float* rwse_b = (const float*)d_in[8];
    const float* deg_emb = (const float*)d_in[9];
    const float* W1 = (const float*)d_in[10];
    const float* b1 = (const float*)d_in[11];
    const float* W2 = (const float*)d_in[12];
    const float* b2 = (const float*)d_in[13];
    const float* gamma = (const float*)d_in[14];
    const float* beta = (const float*)d_in[15];
    const float* mean = (const float*)d_in[16];
    const float* var = (const float*)d_in[17];

    int N = in_sizes[0];
    int E = in_sizes[1] / 2;
    int RWSE = in_sizes[3] / N;
    int DEG = in_sizes[9] / DD;
    int L = in_sizes[10] / (DD * DD);

    // resolve device addresses of __device__ globals (host symbol != device ptr)
    float* d_gh = 0;
    cudaGetSymbolAddress((void**)&d_gh, g_h);

    long outRows = (long)out_size / DD;
    bool both = (outRows > (long)N);
    int G = both ? (int)(outRows - N) : (int)outRows;

    float* pooled = (float*)d_out;
    float* hout = both ? (pooled + (long)G * DD) : d_gh;

    cudaFuncSetAttribute(k_mlp2, cudaFuncAttributeMaxDynamicSharedMemorySize, SMEM_MLP2);

    // (1) degree histogram + zero(pooled,g_comb) + embedding init + weight prep
    int EB = (E + 1023) / 1024;
    int NBi = (N + 7) / 8;
    k_count_init<<<EB + NBi + 2 * L, 256>>>(edge_index, feat_id, indeg, rwse,
                                            value_W, value_b, rwse_W, rwse_b, deg_emb,
                                            W1, W2, pooled, G * DD,
                                            N, E, RWSE, DEG - 1, EB, NBi);

    // (2) single-pass rowptr scan (decoupled lookback; self-cleans g_cnt)
    int NB = (N + 511) / 512;
    k_scan<<<NB, 512>>>(N, NB);

    // (3) CSR fill (4 edges/thread)
    k_fill<<<(E + 1023) / 1024, 256>>>(edge_index, edge_index + E, E);

    // (4..) GIN layers: gather (launch #4 = profiled) + fp16 2-term 2-GEMM MLP
    int ntiles = (N + 127) / 128;
    int lgrid = ntiles < 148 ? ntiles : 148;
    for (int l = 0; l < L; l++) {
        bool last = (l == L - 1);
        k_agg<<<(N + 7) / 8, 256>>>(N);
        k_mlp2<<<lgrid, 512, SMEM_MLP2>>>(last ? hout : d_gh, l,
                                          b1 + l * DD,
                                          gamma + l * DD, beta + l * DD,
                                          mean + l * DD, var + l * DD, b2 + l * DD,
                                          batch, pooled, N, last ? 1 : 0);
    }

    // final mean divide (count via binary search on sorted batch)
    k_pooldiv<<<G, 128>>>(pooled, batch, N);
}

// round 15
// speedup vs baseline: 1.2088x; 1.0402x over previous
#include <cuda_runtime.h>
#include <cuda_fp16.h>
#include <cstdint>

// ---------------- problem constants (fixed by the dataset) ----------------
#define NMAX 50000
#define EMAX 600000
#define DD   128
#define GMAX 128
#define PADK 136                        // fp16 per row (pad 8): conflict-free frags
#define TM   64                         // MLP tile rows (M=64 -> 2 CTAs/SM)
#define NT64 ((NMAX + TM - 1) / TM)     // 782 tiles max

// ---------------- scratch (device globals; no allocation allowed) ---------
__device__ __align__(16) float g_h[NMAX * DD];
__device__ int g_cnt[NMAX];                   // zeroed by k_scan after use
__device__ int g_rowptr[NMAX + 1];
__device__ int g_cursor[NMAX];
__device__ int g_srcs[EMAX];
__device__ unsigned long long g_comb[128];    // lookback state; zeroed by k_count_init
// agg output, pre-converted fp16 hi/lo, 64-row tile-major PADK layout
__device__ __align__(16) __half g_aggh[NT64 * TM * PADK];
__device__ __align__(16) __half g_aggl[NT64 * TM * PADK];
// pre-transposed fp16 weights (hi only): [2L][n*128+k]  (B[n][k] = W[k][n])
__device__ __align__(16) __half g_wh[8 * DD * DD];

__device__ __forceinline__ uint32_t fh2(float x, float y) {
    __half2 h = __floats2half2_rn(x, y);
    return *(uint32_t*)&h;
}
__device__ __forceinline__ uint32_t fl2(float x, float y) {
    float rx = x - __half2float(__float2half_rn(x));
    float ry = y - __half2float(__float2half_rn(y));
    return fh2(rx, ry);
}
__device__ __forceinline__ uint32_t smem_u32(const void* p) {
    uint32_t a;
    asm("{ .reg .u64 t; cvta.to.shared.u64 t, %1; cvt.u32.u64 %0, t; }"
        : "=r"(a) : "l"(p));
    return a;
}
__device__ __forceinline__ void cpa16(uint32_t s, const void* g) {
    asm volatile("cp.async.cg.shared.global [%0], [%1], 16;" :: "r"(s), "l"(g));
}
#define CP_COMMIT() asm volatile("cp.async.commit_group;" ::: "memory")
#define CP_WAIT0()  asm volatile("cp.async.wait_group 0;" ::: "memory")

// portable tensor-core mma fp16 (PTX ISA, sm_70+; works on bare sm_103 target)
__device__ __forceinline__ void mma16816(float* c, const uint32_t* a, const uint32_t* b) {
    asm volatile(
        "mma.sync.aligned.m16n8k16.row.col.f32.f16.f16.f32 "
        "{%0,%1,%2,%3}, {%4,%5,%6,%7}, {%8,%9}, {%0,%1,%2,%3};"
        : "+f"(c[0]), "+f"(c[1]), "+f"(c[2]), "+f"(c[3])
        : "r"(a[0]), "r"(a[1]), "r"(a[2]), "r"(a[3]), "r"(b[0]), "r"(b[1]));
}

// ---------------- kernels ----------------------------------------------------

// fused: [0,EB) degree histogram (4 edges/thr) + zero pooled/g_comb
//        [EB,EB+NBi) embedding init | rest: weight transpose + fp16 quantize
__global__ void k_count_init(const int* __restrict__ edge_index,
                             const int* __restrict__ feat_id,
                             const int* __restrict__ indeg,
                             const float* __restrict__ rwse,
                             const float* __restrict__ value_W,
                             const float* __restrict__ value_b,
                             const float* __restrict__ rwse_W,
                             const float* __restrict__ rwse_b,
                             const float* __restrict__ deg_emb,
                             const float* __restrict__ W1,
                             const float* __restrict__ W2,
                             float* __restrict__ pooled, int GD,
                             int N, int E, int RWSE, int DEGM1, int EB, int NBi) {
    if (blockIdx.x < EB) {
        int gi = blockIdx.x * 256 + threadIdx.x;
        if (gi < GD) pooled[gi] = 0.0f;                        // zero graph output
        if (blockIdx.x == 0 && threadIdx.x < 128) g_comb[threadIdx.x] = 0ull;
        const int* dst = edge_index + E;
        int e0 = blockIdx.x * 1024 + threadIdx.x;
#pragma unroll
        for (int k = 0; k < 4; k++) {                          // 4 indep atomic chains
            int e = e0 + k * 256;
            if (e < E) atomicAdd(&g_cnt[dst[e]], 1);
        }
        return;
    }
    if (blockIdx.x >= EB + NBi) {
        // ---- weight transpose + fp16 quantize (hi only) ----
        int m = blockIdx.x - (EB + NBi);     // 0..2L-1
        int l = m >> 1;
        const float* W = (m & 1) ? (W2 + l * DD * DD) : (W1 + l * DD * DD);
        __shared__ float t[32][33];
        int tx = threadIdx.x & 31, ty8 = threadIdx.x >> 5;  // 32 x 8
        for (int tile = 0; tile < 16; tile++) {
            int tr = tile >> 2, tc = tile & 3;
#pragma unroll
            for (int yy = 0; yy < 4; yy++) {
                int y = yy * 8 + ty8;
                t[y][tx] = W[(tr * 32 + y) * DD + tc * 32 + tx];
            }
            __syncthreads();
#pragma unroll
            for (int yy = 0; yy < 4; yy++) {
                int y = yy * 8 + ty8;
                int n = tc * 32 + y, k = tr * 32 + tx;
                g_wh[m * (DD * DD) + n * DD + k] = __float2half_rn(t[tx][y]);
            }
            __syncthreads();
        }
        return;
    }
    // ---- init h ----
    __shared__ float sRW[16 * DD];
    __shared__ float sVB[DD];
    __shared__ float sRB[DD];
    int tid = threadIdx.x;
    for (int i = tid; i < RWSE * DD; i += 256) sRW[i] = rwse_W[i];
    if (tid < DD) { sVB[tid] = value_b[tid]; sRB[tid] = rwse_b[tid]; }
    __syncthreads();

    int n = (blockIdx.x - EB) * 8 + (tid >> 5);
    if (n >= N) return;
    int lane = tid & 31;
    int c = lane * 4;

    int fid = feat_id[n] % 128;
    int dg = indeg[n];
    dg = dg < 0 ? 0 : (dg > DEGM1 ? DEGM1 : dg);

    float4 acc = *(const float4*)(value_W + fid * DD + c);
    float4 de  = *(const float4*)(deg_emb + dg * DD + c);
    acc.x += sVB[c]     + sRB[c]     + de.x;
    acc.y += sVB[c + 1] + sRB[c + 1] + de.y;
    acc.z += sVB[c + 2] + sRB[c + 2] + de.z;
    acc.w += sVB[c + 3] + sRB[c + 3] + de.w;

    const float* rrow = rwse + (long)n * RWSE;
#pragma unroll
    for (int k = 0; k < 16; k++) {
        float r = rrow[k];
        const float* w = sRW + k * DD + c;
        acc.x = fmaf(r, w[0], acc.x);
        acc.y = fmaf(r, w[1], acc.y);
        acc.z = fmaf(r, w[2], acc.z);
        acc.w = fmaf(r, w[3], acc.w);
    }
    *(float4*)(g_h + (long)n * DD + c) = acc;
}

// single-pass scan: block scan + decoupled lookback; self-cleans g_cnt
__global__ void k_scan(int N, int NB) {
    __shared__ int s[512];
    __shared__ int sexcl;
    int t = threadIdx.x, b = blockIdx.x;
    int i = b * 512 + t;
    int v = (i < N) ? g_cnt[i] : 0;
    s[t] = v;
    __syncthreads();
    for (int off = 1; off < 512; off <<= 1) {
        int x = (t >= off) ? s[t - off] : 0;
        __syncthreads();
        s[t] += x;
        __syncthreads();
    }
    if (t == 511) {
        int total = s[511];
        int excl = 0;
        if (b == 0) {
            *((volatile unsigned long long*)&g_comb[0]) =
                (2ull << 32) | (unsigned)total;
        } else {
            *((volatile unsigned long long*)&g_comb[b]) =
                (1ull << 32) | (unsigned)total;
            int j = b - 1;
            for (;;) {
                unsigned long long c;
                do { c = *((volatile unsigned long long*)&g_comb[j]); }
                while ((c >> 32) == 0);
                excl += (int)(unsigned)c;
                if ((c >> 32) == 2ull) break;
                j--;
            }
            *((volatile unsigned long long*)&g_comb[b]) =
                (2ull << 32) | (unsigned)(excl + total);
        }
        sexcl = excl;
        if (b == NB - 1) g_rowptr[N] = excl + total;
    }
    __syncthreads();
    int ex = sexcl;
    if (i < N) {
        int r = s[t] - v + ex;
        g_rowptr[i] = r;
        g_cursor[i] = r;
        g_cnt[i] = 0;          // self-clean for next kernel_launch call
    }
}

// CSR fill, 4 edges/thread (independent atomic chains hide ATOMG latency)
__global__ void k_fill(const int* __restrict__ src, const int* __restrict__ dst, int E) {
    int e0 = blockIdx.x * 1024 + threadIdx.x;
#pragma unroll
    for (int k = 0; k < 4; k++) {
        int e = e0 + k * 256;
        if (e < E) {
            int d = dst[e];
            int pos = atomicAdd(&g_cursor[d], 1);
            g_srcs[pos] = src[e];
        }
    }
}

// agg[n] = h[n] + sum_{CSR(n)} h[src] (R10 loop — at LTS cap); emit fp16 hi/lo
// into 64-row tile-major layout.
__global__ void k_agg(int N) {
    int n = blockIdx.x * 8 + (threadIdx.x >> 5);
    if (n >= N) return;
    int lane = threadIdx.x & 31;
    const float4* hp = (const float4*)g_h;
    float4 acc = hp[n * 32 + lane];
    int beg = g_rowptr[n], end = g_rowptr[n + 1];
    int e = beg;
    for (; e + 3 < end; e += 4) {
        int s0 = g_srcs[e] * 32 + lane, s1 = g_srcs[e + 1] * 32 + lane;
        int s2 = g_srcs[e + 2] * 32 + lane, s3 = g_srcs[e + 3] * 32 + lane;
        float4 v0 = hp[s0];
        float4 v1 = hp[s1];
        float4 v2 = hp[s2];
        float4 v3 = hp[s3];
        acc.x += (v0.x + v1.x) + (v2.x + v3.x);
        acc.y += (v0.y + v1.y) + (v2.y + v3.y);
        acc.z += (v0.z + v1.z) + (v2.z + v3.z);
        acc.w += (v0.w + v1.w) + (v2.w + v3.w);
    }
    for (; e < end; e++) {
        float4 v0 = hp[g_srcs[e] * 32 + lane];
        acc.x += v0.x; acc.y += v0.y; acc.z += v0.z; acc.w += v0.w;
    }
    int base = (n >> 6) * (TM * PADK) + (n & 63) * PADK + lane * 4;
    uint2 wh, wl;
    wh.x = fh2(acc.x, acc.y); wh.y = fh2(acc.z, acc.w);
    wl.x = fl2(acc.x, acc.y); wl.y = fl2(acc.z, acc.w);
    *(uint2*)(g_aggh + base) = wh;
    *(uint2*)(g_aggl + base) = wl;
}

// ---------------- fused 2-GEMM MLP (fp16 2-term, M=64 tile, 2 CTAs/SM) ------
#define AMATB (TM * PADK * 2)           // 17408 bytes (one 64-row matrix)
#define BMATB (128 * PADK * 2)          // 34816 bytes (one 128-row B matrix)
#define OFF_AH 2048
#define OFF_AL (OFF_AH + AMATB)
#define OFF_B1H (OFF_AH + 2 * AMATB)
#define OFF_B2H (OFF_B1H + BMATB)
#define SMEM_MLP2 (OFF_B2H + BMATB)     // 106496 bytes -> 2 CTAs/SM
#define ANHALF (TM * PADK)              // halfs per A matrix (8704)

// 2-term: D = Ah@Bh + Al@Bh  (A full precision, W quantized fp16)
__device__ __forceinline__ void gemm_tile(const __half* sA, const __half* sBH,
                                          int wm, int wn, int tg, int tq, float (*c)[4]) {
    const __half* sAH = sA;
    const __half* sAL = sA + ANHALF;
#pragma unroll
    for (int i = 0; i < 8; i++) { c[i][0] = c[i][1] = c[i][2] = c[i][3] = 0.f; }
#pragma unroll
    for (int ks = 0; ks < 8; ks++) {
        int k0 = ks * 16 + tq * 2;
        uint32_t ah[2][4], al[2][4], bh[4][2];
#pragma unroll
        for (int mi = 0; mi < 2; mi++) {
            int base = (wm * 32 + mi * 16 + tg) * PADK + k0;
            ah[mi][0] = *(const uint32_t*)(sAH + base);
            ah[mi][1] = *(const uint32_t*)(sAH + base + 8 * PADK);
            ah[mi][2] = *(const uint32_t*)(sAH + base + 8);
            ah[mi][3] = *(const uint32_t*)(sAH + base + 8 * PADK + 8);
            al[mi][0] = *(const uint32_t*)(sAL + base);
            al[mi][1] = *(const uint32_t*)(sAL + base + 8 * PADK);
            al[mi][2] = *(const uint32_t*)(sAL + base + 8);
            al[mi][3] = *(const uint32_t*)(sAL + base + 8 * PADK + 8);
        }
#pragma unroll
        for (int ni = 0; ni < 4; ni++) {
            int base = (wn * 32 + ni * 8 + tg) * PADK + k0;
            bh[ni][0] = *(const uint32_t*)(sBH + base);
            bh[ni][1] = *(const uint32_t*)(sBH + base + 8);
        }
#pragma unroll
        for (int mi = 0; mi < 2; mi++) {
#pragma unroll
            for (int ni = 0; ni < 4; ni++) {
                float* cc = c[mi * 4 + ni];
                mma16816(cc, ah[mi], bh[ni]);
                mma16816(cc, al[mi], bh[ni]);
            }
        }
    }
}

__global__ void __launch_bounds__(256, 2)
k_mlp2(float* __restrict__ out, int l,
       const float* __restrict__ b1,
       const float* __restrict__ gamma, const float* __restrict__ beta,
       const float* __restrict__ mean, const float* __restrict__ var,
       const float* __restrict__ b2,
       const int* __restrict__ batch, float* __restrict__ pooled,
       int N, int do_pool) {
    extern __shared__ char smc[];
    float* sm = (float*)smc;  // [0,128) sc  [128,256) sh  [256,384) b1
    __half* sA   = (__half*)(smc + OFF_AH);
    __half* sB1H = (__half*)(smc + OFF_B1H);
    __half* sB2H = (__half*)(smc + OFF_B2H);
    int tid = threadIdx.x;
    uint32_t sb = smem_u32(smc);

    // header: BN folded into sc/sh, plus b1
    if (tid < 128) {
        float sc = gamma[tid] * rsqrtf(var[tid] + 1e-5f);
        sm[tid]       = sc;
        sm[128 + tid] = (b2[tid] - mean[tid]) * sc + beta[tid];
        sm[256 + tid] = b1[tid];
    }
    // B1/B2 hi load (once per launch)
    {
        const uint4* s1h = (const uint4*)(g_wh + (2 * l) * (DD * DD));
        const uint4* s2h = (const uint4*)(g_wh + (2 * l + 1) * (DD * DD));
        for (int i = tid; i < 2048; i += 256) {
            int n = i >> 4, k8 = (i & 15) << 3;
            int off = n * PADK + k8;
            *(uint4*)(sB1H + off) = s1h[i];
            *(uint4*)(sB2H + off) = s2h[i];
        }
    }

    int w = tid >> 5, lane = tid & 31;
    int wm = w & 1, wn = w >> 1;       // 2(m) x 4(n) warp grid, 32x32 each
    int tg = lane >> 2, tq = lane & 3;

    int ntiles = (N + TM - 1) / TM;
    for (int tile = blockIdx.x; tile < ntiles; tile += gridDim.x) {
        int n0 = tile * TM;
        __syncthreads();   // prev tile's A reads done; B/header visible (1st iter)

        // ---- stage A tile (hi+lo) via cp.async ----
        {
            const char* srcH = (const char*)g_aggh + (size_t)tile * AMATB;
            const char* srcL = (const char*)g_aggl + (size_t)tile * AMATB;
            for (int i = tid; i < AMATB / 16; i += 256) {   // 1088 chunks
                cpa16(sb + OFF_AH + i * 16, srcH + i * 16);
                cpa16(sb + OFF_AL + i * 16, srcL + i * 16);
            }
            CP_COMMIT();
            CP_WAIT0();
        }
        __syncthreads();

        // ---- GEMM1: t = relu(agg @ W1 + b1) ----
        float c[8][4];
        gemm_tile(sA, sB1H, wm, wn, tg, tq, c);
        __syncthreads();   // all A reads done before overwrite with t
#pragma unroll
        for (int mi = 0; mi < 2; mi++) {
#pragma unroll
            for (int ni = 0; ni < 4; ni++) {
                int colc = wn * 32 + ni * 8 + tq * 2;
                float bb0 = sm[256 + colc], bb1 = sm[256 + colc + 1];
                const float* cc = c[mi * 4 + ni];
                int r0 = wm * 32 + mi * 16 + tg;
                float t0 = fmaxf(cc[0] + bb0, 0.f), t1 = fmaxf(cc[1] + bb1, 0.f);
                float t2 = fmaxf(cc[2] + bb0, 0.f), t3 = fmaxf(cc[3] + bb1, 0.f);
                *(uint32_t*)(sA + r0 * PADK + colc)               = fh2(t0, t1);
                *(uint32_t*)(sA + ANHALF + r0 * PADK + colc)      = fl2(t0, t1);
                *(uint32_t*)(sA + (r0 + 8) * PADK + colc)         = fh2(t2, t3);
                *(uint32_t*)(sA + ANHALF + (r0 + 8) * PADK + colc)= fl2(t2, t3);
            }
        }
        __syncthreads();

        // ---- GEMM2: h = relu(BN(t @ W2 + b2)) (+pool) ----
        gemm_tile(sA, sB2H, wm, wn, tg, tq, c);
#pragma unroll
        for (int mi = 0; mi < 2; mi++) {
#pragma unroll
            for (int ni = 0; ni < 4; ni++) {
                int colc = wn * 32 + ni * 8 + tq * 2;
                float sc0 = sm[colc], sc1 = sm[colc + 1];
                float sh0 = sm[128 + colc], sh1 = sm[128 + colc + 1];
                const float* cc = c[mi * 4 + ni];
                int r0 = n0 + wm * 32 + mi * 16 + tg;
                int r1 = r0 + 8;
                if (r0 < N) {
                    float2 o;
                    o.x = fmaxf(fmaf(cc[0], sc0, sh0), 0.f);
                    o.y = fmaxf(fmaf(cc[1], sc1, sh1), 0.f);
                    *(float2*)(out + (long)r0 * DD + colc) = o;
                    if (do_pool) {
                        int g = batch[r0];
                        atomicAdd(pooled + g * DD + colc, o.x);
                        atomicAdd(pooled + g * DD + colc + 1, o.y);
                    }
                }
                if (r1 < N) {
                    float2 o;
                    o.x = fmaxf(fmaf(cc[2], sc0, sh0), 0.f);
                    o.y = fmaxf(fmaf(cc[3], sc1, sh1), 0.f);
                    *(float2*)(out + (long)r1 * DD + colc) = o;
                    if (do_pool) {
                        int g = batch[r1];
                        atomicAdd(pooled + g * DD + colc, o.x);
                        atomicAdd(pooled + g * DD + colc + 1, o.y);
                    }
                }
            }
        }
    }
}

// mean divide; per-graph count via binary search on the SORTED batch array
__global__ void k_pooldiv(float* pooled, const int* __restrict__ batch, int N) {
    __shared__ int scount;
    int g = blockIdx.x;
    if (threadIdx.x == 0) {
        int lo = 0, hi = N;
        while (lo < hi) { int m = (lo + hi) >> 1; if (batch[m] < g) lo = m + 1; else hi = m; }
        int lo2_ = lo, hi2_ = N;
        while (lo2_ < hi2_) { int m = (lo2_ + hi2_) >> 1; if (batch[m] <= g) lo2_ = m + 1; else hi2_ = m; }
        scount = lo2_ - lo;
    }
    __syncthreads();
    float cnt = fmaxf((float)scount, 1.0f);
    pooled[g * DD + threadIdx.x] /= cnt;
}

// ---------------- launcher --------------------------------------------------
extern "C" void kernel_launch(void* const* d_in, const int* in_sizes, int n_in,
                              void* d_out, int out_size) {
    const int*   feat_id = (const int*)d_in[0];
    const int*   edge_index = (const int*)d_in[1];
    const int*   batch = (const int*)d_in[2];
    const float* rwse = (const float*)d_in[3];
    const int*   indeg = (const int*)d_in[4];
    const float* value_W = (const float*)d_in[5];
    const float* value_b = (const float*)d_in[6];
    const float* rwse_W = (const float*)d_in[7];
    const float* rwse_b = (const float*)d_in[8];
    const float* deg_emb = (const float*)d_in[9];
    const float* W1 = (const float*)d_in[10];
    const float* b1 = (const float*)d_in[11];
    const float* W2 = (const float*)d_in[12];
    const float* b2 = (const float*)d_in[13];
    const float* gamma = (const float*)d_in[14];
    const float* beta = (const float*)d_in[15];
    const float* mean = (const float*)d_in[16];
    const float* var = (const float*)d_in[17];

    int N = in_sizes[0];
    int E = in_sizes[1] / 2;
    int RWSE = in_sizes[3] / N;
    int DEG = in_sizes[9] / DD;
    int L = in_sizes[10] / (DD * DD);

    // resolve device addresses of __device__ globals (host symbol != device ptr)
    float* d_gh = 0;
    cudaGetSymbolAddress((void**)&d_gh, g_h);

    long outRows = (long)out_size / DD;
    bool both = (outRows > (long)N);
    int G = both ? (int)(outRows - N) : (int)outRows;

    float* pooled = (float*)d_out;
    float* hout = both ? (pooled + (long)G * DD) : d_gh;

    cudaFuncSetAttribute(k_mlp2, cudaFuncAttributeMaxDynamicSharedMemorySize, SMEM_MLP2);

    // (1) degree histogram + zero(pooled,g_comb) + embedding init + weight prep
    int EB = (E + 1023) / 1024;
    int NBi = (N + 7) / 8;
    k_count_init<<<EB + NBi + 2 * L, 256>>>(edge_index, feat_id, indeg, rwse,
                                            value_W, value_b, rwse_W, rwse_b, deg_emb,
                                            W1, W2, pooled, G * DD,
                                            N, E, RWSE, DEG - 1, EB, NBi);

    // (2) single-pass rowptr scan (decoupled lookback; self-cleans g_cnt)
    int NB = (N + 511) / 512;
    k_scan<<<NB, 512>>>(N, NB);

    // (3) CSR fill (4 edges/thread)
    k_fill<<<(E + 1023) / 1024, 256>>>(edge_index, edge_index + E, E);

    // (4..) GIN layers: gather (launch #4 = profiled) + fp16 2-term MLP (M=64)
    int ntiles = (N + TM - 1) / TM;
    int lgrid = ntiles < 296 ? ntiles : 296;
    for (int l = 0; l < L; l++) {
        bool last = (l == L - 1);
        k_agg<<<(N + 7) / 8, 256>>>(N);
        k_mlp2<<<lgrid, 256, SMEM_MLP2>>>(last ? hout : d_gh, l,
                                          b1 + l * DD,
                                          gamma + l * DD, beta + l * DD,
                                          mean + l * DD, var + l * DD, b2 + l * DD,
                                          batch, pooled, N, last ? 1 : 0);
    }

    // final mean divide (count via binary search on sorted batch)
    k_pooldiv<<<G, 128>>>(pooled, batch, N);
}

// round 16
// speedup vs baseline: 1.2889x; 1.0662x over previous
#include <cuda_runtime.h>
#include <cuda_fp16.h>
#include <cstdint>

// ---------------- problem constants (fixed by the dataset) ----------------
#define NMAX 50000
#define EMAX 600000
#define DD   128
#define GMAX 128
#define PADK 136                        // fp16 per row (pad 8): conflict-free frags
#define TM   64                         // MLP tile rows (M=64 -> 2 CTAs/SM)
#define NT64 ((NMAX + TM - 1) / TM)     // 782 tiles max

// ---------------- scratch (device globals; no allocation allowed) ---------
__device__ __align__(16) float g_h[NMAX * DD];       // fp32 final-h fallback only
__device__ __align__(16) __half g_hh[NMAX * DD];     // fp16 intermediate h
__device__ int g_cnt[NMAX];                   // zeroed by k_scan after use
__device__ int g_rowptr[NMAX + 1];
__device__ int g_cursor[NMAX];
__device__ int g_srcs[EMAX];
__device__ unsigned long long g_comb[128];    // lookback state; zeroed by k_count_init
// agg output, pre-converted fp16 hi/lo, 64-row tile-major PADK layout
__device__ __align__(16) __half g_aggh[NT64 * TM * PADK];
__device__ __align__(16) __half g_aggl[NT64 * TM * PADK];
// pre-transposed fp16 weights (hi only): [2L][n*128+k]  (B[n][k] = W[k][n])
__device__ __align__(16) __half g_wh[8 * DD * DD];

__device__ __forceinline__ uint32_t fh2(float x, float y) {
    __half2 h = __floats2half2_rn(x, y);
    return *(uint32_t*)&h;
}
__device__ __forceinline__ uint32_t fl2(float x, float y) {
    float rx = x - __half2float(__float2half_rn(x));
    float ry = y - __half2float(__float2half_rn(y));
    return fh2(rx, ry);
}
__device__ __forceinline__ uint32_t smem_u32(const void* p) {
    uint32_t a;
    asm("{ .reg .u64 t; cvta.to.shared.u64 t, %1; cvt.u32.u64 %0, t; }"
        : "=r"(a) : "l"(p));
    return a;
}
__device__ __forceinline__ void cpa16(uint32_t s, const void* g) {
    asm volatile("cp.async.cg.shared.global [%0], [%1], 16;" :: "r"(s), "l"(g));
}
#define CP_COMMIT() asm volatile("cp.async.commit_group;" ::: "memory")
#define CP_WAIT0()  asm volatile("cp.async.wait_group 0;" ::: "memory")

// portable tensor-core mma fp16 (PTX ISA, sm_70+; works on bare sm_103 target)
__device__ __forceinline__ void mma16816(float* c, const uint32_t* a, const uint32_t* b) {
    asm volatile(
        "mma.sync.aligned.m16n8k16.row.col.f32.f16.f16.f32 "
        "{%0,%1,%2,%3}, {%4,%5,%6,%7}, {%8,%9}, {%0,%1,%2,%3};"
        : "+f"(c[0]), "+f"(c[1]), "+f"(c[2]), "+f"(c[3])
        : "r"(a[0]), "r"(a[1]), "r"(a[2]), "r"(a[3]), "r"(b[0]), "r"(b[1]));
}

// ---------------- kernels ----------------------------------------------------

// fused: [0,EB) degree histogram (4 edges/thr) + zero pooled/g_comb
//        [EB,EB+NBi) embedding init (fp16 h) | rest: weight transpose + quantize
__global__ void k_count_init(const int* __restrict__ edge_index,
                             const int* __restrict__ feat_id,
                             const int* __restrict__ indeg,
                             const float* __restrict__ rwse,
                             const float* __restrict__ value_W,
                             const float* __restrict__ value_b,
                             const float* __restrict__ rwse_W,
                             const float* __restrict__ rwse_b,
                             const float* __restrict__ deg_emb,
                             const float* __restrict__ W1,
                             const float* __restrict__ W2,
                             float* __restrict__ pooled, int GD,
                             int N, int E, int RWSE, int DEGM1, int EB, int NBi) {
    if (blockIdx.x < EB) {
        int gi = blockIdx.x * 256 + threadIdx.x;
        if (gi < GD) pooled[gi] = 0.0f;                        // zero graph output
        if (blockIdx.x == 0 && threadIdx.x < 128) g_comb[threadIdx.x] = 0ull;
        const int* dst = edge_index + E;
        int e0 = blockIdx.x * 1024 + threadIdx.x;
#pragma unroll
        for (int k = 0; k < 4; k++) {                          // 4 indep atomic chains
            int e = e0 + k * 256;
            if (e < E) atomicAdd(&g_cnt[dst[e]], 1);
        }
        return;
    }
    if (blockIdx.x >= EB + NBi) {
        // ---- weight transpose + fp16 quantize (hi only) ----
        int m = blockIdx.x - (EB + NBi);     // 0..2L-1
        int l = m >> 1;
        const float* W = (m & 1) ? (W2 + l * DD * DD) : (W1 + l * DD * DD);
        __shared__ float t[32][33];
        int tx = threadIdx.x & 31, ty8 = threadIdx.x >> 5;  // 32 x 8
        for (int tile = 0; tile < 16; tile++) {
            int tr = tile >> 2, tc = tile & 3;
#pragma unroll
            for (int yy = 0; yy < 4; yy++) {
                int y = yy * 8 + ty8;
                t[y][tx] = W[(tr * 32 + y) * DD + tc * 32 + tx];
            }
            __syncthreads();
#pragma unroll
            for (int yy = 0; yy < 4; yy++) {
                int y = yy * 8 + ty8;
                int n = tc * 32 + y, k = tr * 32 + tx;
                g_wh[m * (DD * DD) + n * DD + k] = __float2half_rn(t[tx][y]);
            }
            __syncthreads();
        }
        return;
    }
    // ---- init h (fp16) ----
    __shared__ float sRW[16 * DD];
    __shared__ float sVB[DD];
    __shared__ float sRB[DD];
    int tid = threadIdx.x;
    for (int i = tid; i < RWSE * DD; i += 256) sRW[i] = rwse_W[i];
    if (tid < DD) { sVB[tid] = value_b[tid]; sRB[tid] = rwse_b[tid]; }
    __syncthreads();

    int n = (blockIdx.x - EB) * 8 + (tid >> 5);
    if (n >= N) return;
    int lane = tid & 31;
    int c = lane * 4;

    int fid = feat_id[n] % 128;
    int dg = indeg[n];
    dg = dg < 0 ? 0 : (dg > DEGM1 ? DEGM1 : dg);

    float4 acc = *(const float4*)(value_W + fid * DD + c);
    float4 de  = *(const float4*)(deg_emb + dg * DD + c);
    acc.x += sVB[c]     + sRB[c]     + de.x;
    acc.y += sVB[c + 1] + sRB[c + 1] + de.y;
    acc.z += sVB[c + 2] + sRB[c + 2] + de.z;
    acc.w += sVB[c + 3] + sRB[c + 3] + de.w;

    const float* rrow = rwse + (long)n * RWSE;
#pragma unroll
    for (int k = 0; k < 16; k++) {
        float r = rrow[k];
        const float* w = sRW + k * DD + c;
        acc.x = fmaf(r, w[0], acc.x);
        acc.y = fmaf(r, w[1], acc.y);
        acc.z = fmaf(r, w[2], acc.z);
        acc.w = fmaf(r, w[3], acc.w);
    }
    uint2 hv;
    hv.x = fh2(acc.x, acc.y);
    hv.y = fh2(acc.z, acc.w);
    *(uint2*)(g_hh + n * DD + c) = hv;
}

// single-pass scan: block scan + decoupled lookback; self-cleans g_cnt
__global__ void k_scan(int N, int NB) {
    __shared__ int s[512];
    __shared__ int sexcl;
    int t = threadIdx.x, b = blockIdx.x;
    int i = b * 512 + t;
    int v = (i < N) ? g_cnt[i] : 0;
    s[t] = v;
    __syncthreads();
    for (int off = 1; off < 512; off <<= 1) {
        int x = (t >= off) ? s[t - off] : 0;
        __syncthreads();
        s[t] += x;
        __syncthreads();
    }
    if (t == 511) {
        int total = s[511];
        int excl = 0;
        if (b == 0) {
            *((volatile unsigned long long*)&g_comb[0]) =
                (2ull << 32) | (unsigned)total;
        } else {
            *((volatile unsigned long long*)&g_comb[b]) =
                (1ull << 32) | (unsigned)total;
            int j = b - 1;
            for (;;) {
                unsigned long long c;
                do { c = *((volatile unsigned long long*)&g_comb[j]); }
                while ((c >> 32) == 0);
                excl += (int)(unsigned)c;
                if ((c >> 32) == 2ull) break;
                j--;
            }
            *((volatile unsigned long long*)&g_comb[b]) =
                (2ull << 32) | (unsigned)(excl + total);
        }
        sexcl = excl;
        if (b == NB - 1) g_rowptr[N] = excl + total;
    }
    __syncthreads();
    int ex = sexcl;
    if (i < N) {
        int r = s[t] - v + ex;
        g_rowptr[i] = r;
        g_cursor[i] = r;
        g_cnt[i] = 0;          // self-clean for next kernel_launch call
    }
}

// CSR fill, 4 edges/thread (independent atomic chains hide ATOMG latency)
__global__ void k_fill(const int* __restrict__ src, const int* __restrict__ dst, int E) {
    int e0 = blockIdx.x * 1024 + threadIdx.x;
#pragma unroll
    for (int k = 0; k < 4; k++) {
        int e = e0 + k * 256;
        if (e < E) {
            int d = dst[e];
            int pos = atomicAdd(&g_cursor[d], 1);
            g_srcs[pos] = src[e];
        }
    }
}

// agg[n] = h[n] + sum_{CSR(n)} h[src] — fp16 h gather (256 B/row), fp32 accum;
// emit fp16 hi/lo into 64-row tile-major layout.
__global__ void k_agg(int N) {
    int n = blockIdx.x * 8 + (threadIdx.x >> 5);
    if (n >= N) return;
    int lane = threadIdx.x & 31;
    const uint2* hp = (const uint2*)g_hh;          // 32 uint2 per 128-half row
    float4 acc;
    {
        uint2 v = hp[n * 32 + lane];
        float2 f0 = __half22float2(*(__half2*)&v.x);
        float2 f1 = __half22float2(*(__half2*)&v.y);
        acc.x = f0.x; acc.y = f0.y; acc.z = f1.x; acc.w = f1.y;
    }
    int beg = g_rowptr[n], end = g_rowptr[n + 1];
    int e = beg;
    for (; e + 3 < end; e += 4) {
        int s0 = g_srcs[e] * 32 + lane, s1 = g_srcs[e + 1] * 32 + lane;
        int s2 = g_srcs[e + 2] * 32 + lane, s3 = g_srcs[e + 3] * 32 + lane;
        uint2 v0 = hp[s0];
        uint2 v1 = hp[s1];
        uint2 v2 = hp[s2];
        uint2 v3 = hp[s3];
        float2 a0 = __half22float2(*(__half2*)&v0.x), b0 = __half22float2(*(__half2*)&v0.y);
        float2 a1 = __half22float2(*(__half2*)&v1.x), b1 = __half22float2(*(__half2*)&v1.y);
        float2 a2 = __half22float2(*(__half2*)&v2.x), b2 = __half22float2(*(__half2*)&v2.y);
        float2 a3 = __half22float2(*(__half2*)&v3.x), b3 = __half22float2(*(__half2*)&v3.y);
        acc.x += (a0.x + a1.x) + (a2.x + a3.x);
        acc.y += (a0.y + a1.y) + (a2.y + a3.y);
        acc.z += (b0.x + b1.x) + (b2.x + b3.x);
        acc.w += (b0.y + b1.y) + (b2.y + b3.y);
    }
    for (; e < end; e++) {
        uint2 v0 = hp[g_srcs[e] * 32 + lane];
        float2 a0 = __half22float2(*(__half2*)&v0.x), b0 = __half22float2(*(__half2*)&v0.y);
        acc.x += a0.x; acc.y += a0.y; acc.z += b0.x; acc.w += b0.y;
    }
    int base = (n >> 6) * (TM * PADK) + (n & 63) * PADK + lane * 4;
    uint2 wh, wl;
    wh.x = fh2(acc.x, acc.y); wh.y = fh2(acc.z, acc.w);
    wl.x = fl2(acc.x, acc.y); wl.y = fl2(acc.z, acc.w);
    *(uint2*)(g_aggh + base) = wh;
    *(uint2*)(g_aggl + base) = wl;
}

// ---------------- fused 2-GEMM MLP (fp16 2-term, M=64 tile, 2 CTAs/SM) ------
#define AMATB (TM * PADK * 2)           // 17408 bytes (one 64-row matrix)
#define BMATB (128 * PADK * 2)          // 34816 bytes (one 128-row B matrix)
#define OFF_AH 2048
#define OFF_AL (OFF_AH + AMATB)
#define OFF_B1H (OFF_AH + 2 * AMATB)
#define OFF_B2H (OFF_B1H + BMATB)
#define SMEM_MLP2 (OFF_B2H + BMATB)     // 106496 bytes -> 2 CTAs/SM
#define ANHALF (TM * PADK)              // halfs per A matrix (8704)

// 2-term: D = Ah@Bh + Al@Bh  (A full precision, W quantized fp16)
__device__ __forceinline__ void gemm_tile(const __half* sA, const __half* sBH,
                                          int wm, int wn, int tg, int tq, float (*c)[4]) {
    const __half* sAH = sA;
    const __half* sAL = sA + ANHALF;
#pragma unroll
    for (int i = 0; i < 8; i++) { c[i][0] = c[i][1] = c[i][2] = c[i][3] = 0.f; }
#pragma unroll
    for (int ks = 0; ks < 8; ks++) {
        int k0 = ks * 16 + tq * 2;
        uint32_t ah[2][4], al[2][4], bh[4][2];
#pragma unroll
        for (int mi = 0; mi < 2; mi++) {
            int base = (wm * 32 + mi * 16 + tg) * PADK + k0;
            ah[mi][0] = *(const uint32_t*)(sAH + base);
            ah[mi][1] = *(const uint32_t*)(sAH + base + 8 * PADK);
            ah[mi][2] = *(const uint32_t*)(sAH + base + 8);
            ah[mi][3] = *(const uint32_t*)(sAH + base + 8 * PADK + 8);
            al[mi][0] = *(const uint32_t*)(sAL + base);
            al[mi][1] = *(const uint32_t*)(sAL + base + 8 * PADK);
            al[mi][2] = *(const uint32_t*)(sAL + base + 8);
            al[mi][3] = *(const uint32_t*)(sAL + base + 8 * PADK + 8);
        }
#pragma unroll
        for (int ni = 0; ni < 4; ni++) {
            int base = (wn * 32 + ni * 8 + tg) * PADK + k0;
            bh[ni][0] = *(const uint32_t*)(sBH + base);
            bh[ni][1] = *(const uint32_t*)(sBH + base + 8);
        }
#pragma unroll
        for (int mi = 0; mi < 2; mi++) {
#pragma unroll
            for (int ni = 0; ni < 4; ni++) {
                float* cc = c[mi * 4 + ni];
                mma16816(cc, ah[mi], bh[ni]);
                mma16816(cc, al[mi], bh[ni]);
            }
        }
    }
}

__global__ void __launch_bounds__(256, 2)
k_mlp2(float* __restrict__ out, __half* __restrict__ outh, int l,
       const float* __restrict__ b1,
       const float* __restrict__ gamma, const float* __restrict__ beta,
       const float* __restrict__ mean, const float* __restrict__ var,
       const float* __restrict__ b2,
       const int* __restrict__ batch, float* __restrict__ pooled,
       int N, int last) {
    extern __shared__ char smc[];
    float* sm = (float*)smc;  // [0,128) sc  [128,256) sh  [256,384) b1
    __half* sA   = (__half*)(smc + OFF_AH);
    __half* sB1H = (__half*)(smc + OFF_B1H);
    __half* sB2H = (__half*)(smc + OFF_B2H);
    int tid = threadIdx.x;
    uint32_t sb = smem_u32(smc);

    // header: BN folded into sc/sh, plus b1
    if (tid < 128) {
        float sc = gamma[tid] * rsqrtf(var[tid] + 1e-5f);
        sm[tid]       = sc;
        sm[128 + tid] = (b2[tid] - mean[tid]) * sc + beta[tid];
        sm[256 + tid] = b1[tid];
    }
    // B1/B2 hi load (once per launch)
    {
        const uint4* s1h = (const uint4*)(g_wh + (2 * l) * (DD * DD));
        const uint4* s2h = (const uint4*)(g_wh + (2 * l + 1) * (DD * DD));
        for (int i = tid; i < 2048; i += 256) {
            int n = i >> 4, k8 = (i & 15) << 3;
            int off = n * PADK + k8;
            *(uint4*)(sB1H + off) = s1h[i];
            *(uint4*)(sB2H + off) = s2h[i];
        }
    }

    int w = tid >> 5, lane = tid & 31;
    int wm = w & 1, wn = w >> 1;       // 2(m) x 4(n) warp grid, 32x32 each
    int tg = lane >> 2, tq = lane & 3;

    int ntiles = (N + TM - 1) / TM;
    for (int tile = blockIdx.x; tile < ntiles; tile += gridDim.x) {
        int n0 = tile * TM;
        __syncthreads();   // prev tile's A reads done; B/header visible (1st iter)

        // ---- stage A tile (hi+lo) via cp.async ----
        {
            const char* srcH = (const char*)g_aggh + (size_t)tile * AMATB;
            const char* srcL = (const char*)g_aggl + (size_t)tile * AMATB;
            for (int i = tid; i < AMATB / 16; i += 256) {   // 1088 chunks
                cpa16(sb + OFF_AH + i * 16, srcH + i * 16);
                cpa16(sb + OFF_AL + i * 16, srcL + i * 16);
            }
            CP_COMMIT();
            CP_WAIT0();
        }
        __syncthreads();

        // ---- GEMM1: t = relu(agg @ W1 + b1) ----
        float c[8][4];
        gemm_tile(sA, sB1H, wm, wn, tg, tq, c);
        __syncthreads();   // all A reads done before overwrite with t
#pragma unroll
        for (int mi = 0; mi < 2; mi++) {
#pragma unroll
            for (int ni = 0; ni < 4; ni++) {
                int colc = wn * 32 + ni * 8 + tq * 2;
                float bb0 = sm[256 + colc], bb1 = sm[256 + colc + 1];
                const float* cc = c[mi * 4 + ni];
                int r0 = wm * 32 + mi * 16 + tg;
                float t0 = fmaxf(cc[0] + bb0, 0.f), t1 = fmaxf(cc[1] + bb1, 0.f);
                float t2 = fmaxf(cc[2] + bb0, 0.f), t3 = fmaxf(cc[3] + bb1, 0.f);
                *(uint32_t*)(sA + r0 * PADK + colc)               = fh2(t0, t1);
                *(uint32_t*)(sA + ANHALF + r0 * PADK + colc)      = fl2(t0, t1);
                *(uint32_t*)(sA + (r0 + 8) * PADK + colc)         = fh2(t2, t3);
                *(uint32_t*)(sA + ANHALF + (r0 + 8) * PADK + colc)= fl2(t2, t3);
            }
        }
        __syncthreads();

        // ---- GEMM2: h = relu(BN(t @ W2 + b2)) ----
        gemm_tile(sA, sB2H, wm, wn, tg, tq, c);
#pragma unroll
        for (int mi = 0; mi < 2; mi++) {
#pragma unroll
            for (int ni = 0; ni < 4; ni++) {
                int colc = wn * 32 + ni * 8 + tq * 2;
                float sc0 = sm[colc], sc1 = sm[colc + 1];
                float sh0 = sm[128 + colc], sh1 = sm[128 + colc + 1];
                const float* cc = c[mi * 4 + ni];
                int r0 = n0 + wm * 32 + mi * 16 + tg;
                int r1 = r0 + 8;
                float2 o0, o1;
                o0.x = fmaxf(fmaf(cc[0], sc0, sh0), 0.f);
                o0.y = fmaxf(fmaf(cc[1], sc1, sh1), 0.f);
                o1.x = fmaxf(fmaf(cc[2], sc0, sh0), 0.f);
                o1.y = fmaxf(fmaf(cc[3], sc1, sh1), 0.f);
                if (last) {
                    if (r0 < N) {
                        *(float2*)(out + (long)r0 * DD + colc) = o0;
                        int g = batch[r0];
                        atomicAdd(pooled + g * DD + colc, o0.x);
                        atomicAdd(pooled + g * DD + colc + 1, o0.y);
                    }
                    if (r1 < N) {
                        *(float2*)(out + (long)r1 * DD + colc) = o1;
                        int g = batch[r1];
                        atomicAdd(pooled + g * DD + colc, o1.x);
                        atomicAdd(pooled + g * DD + colc + 1, o1.y);
                    }
                } else {
                    if (r0 < N) {
                        uint32_t hv = fh2(o0.x, o0.y);
                        *(uint32_t*)(outh + r0 * DD + colc) = hv;
                    }
                    if (r1 < N) {
                        uint32_t hv = fh2(o1.x, o1.y);
                        *(uint32_t*)(outh + r1 * DD + colc) = hv;
                    }
                }
            }
        }
    }
}

// mean divide; per-graph count via binary search on the SORTED batch array
__global__ void k_pooldiv(float* pooled, const int* __restrict__ batch, int N) {
    __shared__ int scount;
    int g = blockIdx.x;
    if (threadIdx.x == 0) {
        int lo = 0, hi = N;
        while (lo < hi) { int m = (lo + hi) >> 1; if (batch[m] < g) lo = m + 1; else hi = m; }
        int lo2_ = lo, hi2_ = N;
        while (lo2_ < hi2_) { int m = (lo2_ + hi2_) >> 1; if (batch[m] <= g) lo2_ = m + 1; else hi2_ = m; }
        scount = lo2_ - lo;
    }
    __syncthreads();
    float cnt = fmaxf((float)scount, 1.0f);
    pooled[g * DD + threadIdx.x] /= cnt;
}

// ---------------- launcher --------------------------------------------------
extern "C" void kernel_launch(void* const* d_in, const int* in_sizes, int n_in,
                              void* d_out, int out_size) {
    const int*   feat_id = (const int*)d_in[0];
    const int*   edge_index = (const int*)d_in[1];
    const int*   batch = (const int*)d_in[2];
    const float* rwse = (const float*)d_in[3];
    const int*   indeg = (const int*)d_in[4];
    const float* value_W = (const float*)d_in[5];
    const float* value_b = (const float*)d_in[6];
    const float* rwse_W = (const float*)d_in[7];
    const float* rwse_b = (const float*)d_in[8];
    const float* deg_emb = (const float*)d_in[9];
    const float* W1 = (const float*)d_in[10];
    const float* b1 = (const float*)d_in[11];
    const float* W2 = (const float*)d_in[12];
    const float* b2 = (const float*)d_in[13];
    const float* gamma = (const float*)d_in[14];
    const float* beta = (const float*)d_in[15];
    const float* mean = (const float*)d_in[16];
    const float* var = (const float*)d_in[17];

    int N = in_sizes[0];
    int E = in_sizes[1] / 2;
    int RWSE = in_sizes[3] / N;
    int DEG = in_sizes[9] / DD;
    int L = in_sizes[10] / (DD * DD);

    // resolve device addresses of __device__ globals (host symbol != device ptr)
    float* d_gh = 0;
    __half* d_ghh = 0;
    cudaGetSymbolAddress((void**)&d_gh, g_h);
    cudaGetSymbolAddress((void**)&d_ghh, g_hh);

    long outRows = (long)out_size / DD;
    bool both = (outRows > (long)N);
    int G = both ? (int)(outRows - N) : (int)outRows;

    float* pooled = (float*)d_out;
    float* hout = both ? (pooled + (long)G * DD) : d_gh;

    cudaFuncSetAttribute(k_mlp2, cudaFuncAttributeMaxDynamicSharedMemorySize, SMEM_MLP2);

    // (1) degree histogram + zero(pooled,g_comb) + embedding init + weight prep
    int EB = (E + 1023) / 1024;
    int NBi = (N + 7) / 8;
    k_count_init<<<EB + NBi + 2 * L, 256>>>(edge_index, feat_id, indeg, rwse,
                                            value_W, value_b, rwse_W, rwse_b, deg_emb,
                                            W1, W2, pooled, G * DD,
                                            N, E, RWSE, DEG - 1, EB, NBi);

    // (2) single-pass rowptr scan (decoupled lookback; self-cleans g_cnt)
    int NB = (N + 511) / 512;
    k_scan<<<NB, 512>>>(N, NB);

    // (3) CSR fill (4 edges/thread)
    k_fill<<<(E + 1023) / 1024, 256>>>(edge_index, edge_index + E, E);

    // (4..) GIN layers: fp16-h gather (launch #4 = profiled) + fp16 2-term MLP
    int ntiles = (N + TM - 1) / TM;
    int lgrid = ntiles < 296 ? ntiles : 296;
    for (int l = 0; l < L; l++) {
        bool last = (l == L - 1);
        k_agg<<<(N + 7) / 8, 256>>>(N);
        k_mlp2<<<lgrid, 256, SMEM_MLP2>>>(hout, d_ghh, l,
                                          b1 + l * DD,
                                          gamma + l * DD, beta + l * DD,
                                          mean + l * DD, var + l * DD, b2 + l * DD,
                                          batch, pooled, N, last ? 1 : 0);
    }

    // final mean divide (count via binary search on sorted batch)
    k_pooldiv<<<G, 128>>>(pooled, batch, N);
}

// round 17
// speedup vs baseline: 1.4317x; 1.1108x over previous
#include <cuda_runtime.h>
#include <cuda_fp16.h>
#include <cstdint>

// ---------------- problem constants (fixed by the dataset) ----------------
#define NMAX 50000
#define EMAX 600000
#define DD   128
#define GMAX 128
#define PADK 136                        // fp16 per row (pad 8): conflict-free frags
#define TM   64                         // MLP tile rows (M=64 -> 2 CTAs/SM)
#define NT64 ((NMAX + TM - 1) / TM)     // 782 tiles max

// ---------------- scratch (device globals; no allocation allowed) ---------
__device__ __align__(16) float g_h[NMAX * DD];       // fp32 final-h fallback only
__device__ __align__(16) __half g_hh[NMAX * DD];     // fp16 intermediate h
__device__ int g_cnt[NMAX];                   // zeroed by k_scan after use
__device__ int g_rowptr[NMAX + 1];
__device__ int g_cursor[NMAX];
__device__ int g_srcs[EMAX];
__device__ unsigned long long g_comb[128];    // lookback state; zeroed by k_count_init
// agg output, fp16, 64-row tile-major PADK layout (mlp2's smem image)
__device__ __align__(16) __half g_aggh[NT64 * TM * PADK];
// pre-transposed fp16 weights: [2L][n*128+k]  (B[n][k] = W[k][n])
__device__ __align__(16) __half g_wh[8 * DD * DD];

__device__ __forceinline__ uint32_t fh2(float x, float y) {
    __half2 h = __floats2half2_rn(x, y);
    return *(uint32_t*)&h;
}
__device__ __forceinline__ uint32_t smem_u32(const void* p) {
    uint32_t a;
    asm("{ .reg .u64 t; cvta.to.shared.u64 t, %1; cvt.u32.u64 %0, t; }"
        : "=r"(a) : "l"(p));
    return a;
}
__device__ __forceinline__ void cpa16(uint32_t s, const void* g) {
    asm volatile("cp.async.cg.shared.global [%0], [%1], 16;" :: "r"(s), "l"(g));
}
#define CP_COMMIT() asm volatile("cp.async.commit_group;" ::: "memory")
#define CP_WAIT0()  asm volatile("cp.async.wait_group 0;" ::: "memory")

// portable tensor-core mma fp16 (PTX ISA, sm_70+; works on bare sm_103 target)
__device__ __forceinline__ void mma16816(float* c, const uint32_t* a, const uint32_t* b) {
    asm volatile(
        "mma.sync.aligned.m16n8k16.row.col.f32.f16.f16.f32 "
        "{%0,%1,%2,%3}, {%4,%5,%6,%7}, {%8,%9}, {%0,%1,%2,%3};"
        : "+f"(c[0]), "+f"(c[1]), "+f"(c[2]), "+f"(c[3])
        : "r"(a[0]), "r"(a[1]), "r"(a[2]), "r"(a[3]), "r"(b[0]), "r"(b[1]));
}

// ---------------- kernels ----------------------------------------------------

// fused: [0,EB) degree histogram (4 edges/thr) + zero pooled/g_comb
//        [EB,EB+NBi) embedding init (fp16 h) | rest: weight transpose + quantize
__global__ void k_count_init(const int* __restrict__ edge_index,
                             const int* __restrict__ feat_id,
                             const int* __restrict__ indeg,
                             const float* __restrict__ rwse,
                             const float* __restrict__ value_W,
                             const float* __restrict__ value_b,
                             const float* __restrict__ rwse_W,
                             const float* __restrict__ rwse_b,
                             const float* __restrict__ deg_emb,
                             const float* __restrict__ W1,
                             const float* __restrict__ W2,
                             float* __restrict__ pooled, int GD,
                             int N, int E, int RWSE, int DEGM1, int EB, int NBi) {
    if (blockIdx.x < EB) {
        int gi = blockIdx.x * 256 + threadIdx.x;
        if (gi < GD) pooled[gi] = 0.0f;                        // zero graph output
        if (blockIdx.x == 0 && threadIdx.x < 128) g_comb[threadIdx.x] = 0ull;
        const int* dst = edge_index + E;
        int e0 = blockIdx.x * 1024 + threadIdx.x;
#pragma unroll
        for (int k = 0; k < 4; k++) {                          // 4 indep atomic chains
            int e = e0 + k * 256;
            if (e < E) atomicAdd(&g_cnt[dst[e]], 1);
        }
        return;
    }
    if (blockIdx.x >= EB + NBi) {
        // ---- weight transpose + fp16 quantize ----
        int m = blockIdx.x - (EB + NBi);     // 0..2L-1
        int l = m >> 1;
        const float* W = (m & 1) ? (W2 + l * DD * DD) : (W1 + l * DD * DD);
        __shared__ float t[32][33];
        int tx = threadIdx.x & 31, ty8 = threadIdx.x >> 5;  // 32 x 8
        for (int tile = 0; tile < 16; tile++) {
            int tr = tile >> 2, tc = tile & 3;
#pragma unroll
            for (int yy = 0; yy < 4; yy++) {
                int y = yy * 8 + ty8;
                t[y][tx] = W[(tr * 32 + y) * DD + tc * 32 + tx];
            }
            __syncthreads();
#pragma unroll
            for (int yy = 0; yy < 4; yy++) {
                int y = yy * 8 + ty8;
                int n = tc * 32 + y, k = tr * 32 + tx;
                g_wh[m * (DD * DD) + n * DD + k] = __float2half_rn(t[tx][y]);
            }
            __syncthreads();
        }
        return;
    }
    // ---- init h (fp16) ----
    __shared__ float sRW[16 * DD];
    __shared__ float sVB[DD];
    __shared__ float sRB[DD];
    int tid = threadIdx.x;
    for (int i = tid; i < RWSE * DD; i += 256) sRW[i] = rwse_W[i];
    if (tid < DD) { sVB[tid] = value_b[tid]; sRB[tid] = rwse_b[tid]; }
    __syncthreads();

    int n = (blockIdx.x - EB) * 8 + (tid >> 5);
    if (n >= N) return;
    int lane = tid & 31;
    int c = lane * 4;

    int fid = feat_id[n] % 128;
    int dg = indeg[n];
    dg = dg < 0 ? 0 : (dg > DEGM1 ? DEGM1 : dg);

    float4 acc = *(const float4*)(value_W + fid * DD + c);
    float4 de  = *(const float4*)(deg_emb + dg * DD + c);
    acc.x += sVB[c]     + sRB[c]     + de.x;
    acc.y += sVB[c + 1] + sRB[c + 1] + de.y;
    acc.z += sVB[c + 2] + sRB[c + 2] + de.z;
    acc.w += sVB[c + 3] + sRB[c + 3] + de.w;

    const float* rrow = rwse + (long)n * RWSE;
#pragma unroll
    for (int k = 0; k < 16; k++) {
        float r = rrow[k];
        const float* w = sRW + k * DD + c;
        acc.x = fmaf(r, w[0], acc.x);
        acc.y = fmaf(r, w[1], acc.y);
        acc.z = fmaf(r, w[2], acc.z);
        acc.w = fmaf(r, w[3], acc.w);
    }
    uint2 hv;
    hv.x = fh2(acc.x, acc.y);
    hv.y = fh2(acc.z, acc.w);
    *(uint2*)(g_hh + n * DD + c) = hv;
}

// single-pass scan: block scan + decoupled lookback; self-cleans g_cnt
__global__ void k_scan(int N, int NB) {
    __shared__ int s[512];
    __shared__ int sexcl;
    int t = threadIdx.x, b = blockIdx.x;
    int i = b * 512 + t;
    int v = (i < N) ? g_cnt[i] : 0;
    s[t] = v;
    __syncthreads();
    for (int off = 1; off < 512; off <<= 1) {
        int x = (t >= off) ? s[t - off] : 0;
        __syncthreads();
        s[t] += x;
        __syncthreads();
    }
    if (t == 511) {
        int total = s[511];
        int excl = 0;
        if (b == 0) {
            *((volatile unsigned long long*)&g_comb[0]) =
                (2ull << 32) | (unsigned)total;
        } else {
            *((volatile unsigned long long*)&g_comb[b]) =
                (1ull << 32) | (unsigned)total;
            int j = b - 1;
            for (;;) {
                unsigned long long c;
                do { c = *((volatile unsigned long long*)&g_comb[j]); }
                while ((c >> 32) == 0);
                excl += (int)(unsigned)c;
                if ((c >> 32) == 2ull) break;
                j--;
            }
            *((volatile unsigned long long*)&g_comb[b]) =
                (2ull << 32) | (unsigned)(excl + total);
        }
        sexcl = excl;
        if (b == NB - 1) g_rowptr[N] = excl + total;
    }
    __syncthreads();
    int ex = sexcl;
    if (i < N) {
        int r = s[t] - v + ex;
        g_rowptr[i] = r;
        g_cursor[i] = r;
        g_cnt[i] = 0;          // self-clean for next kernel_launch call
    }
}

// CSR fill, 4 edges/thread (independent atomic chains hide ATOMG latency)
__global__ void k_fill(const int* __restrict__ src, const int* __restrict__ dst, int E) {
    int e0 = blockIdx.x * 1024 + threadIdx.x;
#pragma unroll
    for (int k = 0; k < 4; k++) {
        int e = e0 + k * 256;
        if (e < E) {
            int d = dst[e];
            int pos = atomicAdd(&g_cursor[d], 1);
            g_srcs[pos] = src[e];
        }
    }
}

// agg[n] = h[n] + sum_{CSR(n)} h[src] — fp16 h gather, fp32 accum; emit fp16
__global__ void k_agg(int N) {
    int n = blockIdx.x * 8 + (threadIdx.x >> 5);
    if (n >= N) return;
    int lane = threadIdx.x & 31;
    const uint2* hp = (const uint2*)g_hh;          // 32 uint2 per 128-half row
    float4 acc;
    {
        uint2 v = hp[n * 32 + lane];
        float2 f0 = __half22float2(*(__half2*)&v.x);
        float2 f1 = __half22float2(*(__half2*)&v.y);
        acc.x = f0.x; acc.y = f0.y; acc.z = f1.x; acc.w = f1.y;
    }
    int beg = g_rowptr[n], end = g_rowptr[n + 1];
    int e = beg;
    for (; e + 3 < end; e += 4) {
        int s0 = g_srcs[e] * 32 + lane, s1 = g_srcs[e + 1] * 32 + lane;
        int s2 = g_srcs[e + 2] * 32 + lane, s3 = g_srcs[e + 3] * 32 + lane;
        uint2 v0 = hp[s0];
        uint2 v1 = hp[s1];
        uint2 v2 = hp[s2];
        uint2 v3 = hp[s3];
        float2 a0 = __half22float2(*(__half2*)&v0.x), b0 = __half22float2(*(__half2*)&v0.y);
        float2 a1 = __half22float2(*(__half2*)&v1.x), b1 = __half22float2(*(__half2*)&v1.y);
        float2 a2 = __half22float2(*(__half2*)&v2.x), b2 = __half22float2(*(__half2*)&v2.y);
        float2 a3 = __half22float2(*(__half2*)&v3.x), b3 = __half22float2(*(__half2*)&v3.y);
        acc.x += (a0.x + a1.x) + (a2.x + a3.x);
        acc.y += (a0.y + a1.y) + (a2.y + a3.y);
        acc.z += (b0.x + b1.x) + (b2.x + b3.x);
        acc.w += (b0.y + b1.y) + (b2.y + b3.y);
    }
    for (; e < end; e++) {
        uint2 v0 = hp[g_srcs[e] * 32 + lane];
        float2 a0 = __half22float2(*(__half2*)&v0.x), b0 = __half22float2(*(__half2*)&v0.y);
        acc.x += a0.x; acc.y += a0.y; acc.z += b0.x; acc.w += b0.y;
    }
    int base = (n >> 6) * (TM * PADK) + (n & 63) * PADK + lane * 4;
    uint2 wh;
    wh.x = fh2(acc.x, acc.y); wh.y = fh2(acc.z, acc.w);
    *(uint2*)(g_aggh + base) = wh;
}

// ---------------- fused 2-GEMM MLP (fp16 single-term, M=64, 2 CTAs/SM) ------
#define AMATB (TM * PADK * 2)           // 17408 bytes (one 64-row A matrix)
#define BMATB (128 * PADK * 2)          // 34816 bytes (one 128-row B matrix)
#define OFF_A 2048
#define OFF_B1H (OFF_A + AMATB)
#define OFF_B2H (OFF_B1H + BMATB)
#define SMEM_MLP2 (OFF_B2H + BMATB)     // 89088 bytes -> 2 CTAs/SM

// single-term: D = A@Bh  (A and W both fp16, fp32 accumulate)
__device__ __forceinline__ void gemm_tile(const __half* sA, const __half* sBH,
                                          int wm, int wn, int tg, int tq, float (*c)[4]) {
#pragma unroll
    for (int i = 0; i < 8; i++) { c[i][0] = c[i][1] = c[i][2] = c[i][3] = 0.f; }
#pragma unroll
    for (int ks = 0; ks < 8; ks++) {
        int k0 = ks * 16 + tq * 2;
        uint32_t ah[2][4], bh[4][2];
#pragma unroll
        for (int mi = 0; mi < 2; mi++) {
            int base = (wm * 32 + mi * 16 + tg) * PADK + k0;
            ah[mi][0] = *(const uint32_t*)(sA + base);
            ah[mi][1] = *(const uint32_t*)(sA + base + 8 * PADK);
            ah[mi][2] = *(const uint32_t*)(sA + base + 8);
            ah[mi][3] = *(const uint32_t*)(sA + base + 8 * PADK + 8);
        }
#pragma unroll
        for (int ni = 0; ni < 4; ni++) {
            int base = (wn * 32 + ni * 8 + tg) * PADK + k0;
            bh[ni][0] = *(const uint32_t*)(sBH + base);
            bh[ni][1] = *(const uint32_t*)(sBH + base + 8);
        }
#pragma unroll
        for (int mi = 0; mi < 2; mi++) {
#pragma unroll
            for (int ni = 0; ni < 4; ni++) {
                mma16816(c[mi * 4 + ni], ah[mi], bh[ni]);
            }
        }
    }
}

__global__ void __launch_bounds__(256, 2)
k_mlp2(float* __restrict__ out, __half* __restrict__ outh, int l,
       const float* __restrict__ b1,
       const float* __restrict__ gamma, const float* __restrict__ beta,
       const float* __restrict__ mean, const float* __restrict__ var,
       const float* __restrict__ b2,
       const int* __restrict__ batch, float* __restrict__ pooled,
       int N, int last) {
    extern __shared__ char smc[];
    float* sm = (float*)smc;  // [0,128) sc  [128,256) sh  [256,384) b1
    __half* sA   = (__half*)(smc + OFF_A);
    __half* sB1H = (__half*)(smc + OFF_B1H);
    __half* sB2H = (__half*)(smc + OFF_B2H);
    int tid = threadIdx.x;
    uint32_t sb = smem_u32(smc);

    // header: BN folded into sc/sh, plus b1
    if (tid < 128) {
        float sc = gamma[tid] * rsqrtf(var[tid] + 1e-5f);
        sm[tid]       = sc;
        sm[128 + tid] = (b2[tid] - mean[tid]) * sc + beta[tid];
        sm[256 + tid] = b1[tid];
    }
    // B1/B2 load (once per launch)
    {
        const uint4* s1h = (const uint4*)(g_wh + (2 * l) * (DD * DD));
        const uint4* s2h = (const uint4*)(g_wh + (2 * l + 1) * (DD * DD));
        for (int i = tid; i < 2048; i += 256) {
            int n = i >> 4, k8 = (i & 15) << 3;
            int off = n * PADK + k8;
            *(uint4*)(sB1H + off) = s1h[i];
            *(uint4*)(sB2H + off) = s2h[i];
        }
    }

    int w = tid >> 5, lane = tid & 31;
    int wm = w & 1, wn = w >> 1;       // 2(m) x 4(n) warp grid, 32x32 each
    int tg = lane >> 2, tq = lane & 3;

    int ntiles = (N + TM - 1) / TM;
    for (int tile = blockIdx.x; tile < ntiles; tile += gridDim.x) {
        int n0 = tile * TM;
        __syncthreads();   // prev tile's A reads done; B/header visible (1st iter)

        // ---- stage A tile via cp.async ----
        {
            const char* srcH = (const char*)g_aggh + (size_t)tile * AMATB;
            for (int i = tid; i < AMATB / 16; i += 256) {   // 1088 chunks
                cpa16(sb + OFF_A + i * 16, srcH + i * 16);
            }
            CP_COMMIT();
            CP_WAIT0();
        }
        __syncthreads();

        // ---- GEMM1: t = relu(agg @ W1 + b1) ----
        float c[8][4];
        gemm_tile(sA, sB1H, wm, wn, tg, tq, c);
        __syncthreads();   // all A reads done before overwrite with t
#pragma unroll
        for (int mi = 0; mi < 2; mi++) {
#pragma unroll
            for (int ni = 0; ni < 4; ni++) {
                int colc = wn * 32 + ni * 8 + tq * 2;
                float bb0 = sm[256 + colc], bb1 = sm[256 + colc + 1];
                const float* cc = c[mi * 4 + ni];
                int r0 = wm * 32 + mi * 16 + tg;
                float t0 = fmaxf(cc[0] + bb0, 0.f), t1 = fmaxf(cc[1] + bb1, 0.f);
                float t2 = fmaxf(cc[2] + bb0, 0.f), t3 = fmaxf(cc[3] + bb1, 0.f);
                *(uint32_t*)(sA + r0 * PADK + colc)       = fh2(t0, t1);
                *(uint32_t*)(sA + (r0 + 8) * PADK + colc) = fh2(t2, t3);
            }
        }
        __syncthreads();

        // ---- GEMM2: h = relu(BN(t @ W2 + b2)) ----
        gemm_tile(sA, sB2H, wm, wn, tg, tq, c);
#pragma unroll
        for (int mi = 0; mi < 2; mi++) {
#pragma unroll
            for (int ni = 0; ni < 4; ni++) {
                int colc = wn * 32 + ni * 8 + tq * 2;
                float sc0 = sm[colc], sc1 = sm[colc + 1];
                float sh0 = sm[128 + colc], sh1 = sm[128 + colc + 1];
                const float* cc = c[mi * 4 + ni];
                int r0 = n0 + wm * 32 + mi * 16 + tg;
                int r1 = r0 + 8;
                float2 o0, o1;
                o0.x = fmaxf(fmaf(cc[0], sc0, sh0), 0.f);
                o0.y = fmaxf(fmaf(cc[1], sc1, sh1), 0.f);
                o1.x = fmaxf(fmaf(cc[2], sc0, sh0), 0.f);
                o1.y = fmaxf(fmaf(cc[3], sc1, sh1), 0.f);
                if (last) {
                    if (r0 < N) {
                        *(float2*)(out + (long)r0 * DD + colc) = o0;
                        int g = batch[r0];
                        atomicAdd(pooled + g * DD + colc, o0.x);
                        atomicAdd(pooled + g * DD + colc + 1, o0.y);
                    }
                    if (r1 < N) {
                        *(float2*)(out + (long)r1 * DD + colc) = o1;
                        int g = batch[r1];
                        atomicAdd(pooled + g * DD + colc, o1.x);
                        atomicAdd(pooled + g * DD + colc + 1, o1.y);
                    }
                } else {
                    if (r0 < N) *(uint32_t*)(outh + r0 * DD + colc) = fh2(o0.x, o0.y);
                    if (r1 < N) *(uint32_t*)(outh + r1 * DD + colc) = fh2(o1.x, o1.y);
                }
            }
        }
    }
}

// mean divide; per-graph count via binary search on the SORTED batch array
__global__ void k_pooldiv(float* pooled, const int* __restrict__ batch, int N) {
    __shared__ int scount;
    int g = blockIdx.x;
    if (threadIdx.x == 0) {
        int lo = 0, hi = N;
        while (lo < hi) { int m = (lo + hi) >> 1; if (batch[m] < g) lo = m + 1; else hi = m; }
        int lo2_ = lo, hi2_ = N;
        while (lo2_ < hi2_) { int m = (lo2_ + hi2_) >> 1; if (batch[m] <= g) lo2_ = m + 1; else hi2_ = m; }
        scount = lo2_ - lo;
    }
    __syncthreads();
    float cnt = fmaxf((float)scount, 1.0f);
    pooled[g * DD + threadIdx.x] /= cnt;
}

// ---------------- launcher --------------------------------------------------
extern "C" void kernel_launch(void* const* d_in, const int* in_sizes, int n_in,
                              void* d_out, int out_size) {
    const int*   feat_id = (const int*)d_in[0];
    const int*   edge_index = (const int*)d_in[1];
    const int*   batch = (const int*)d_in[2];
    const float* rwse = (const float*)d_in[3];
    const int*   indeg = (const int*)d_in[4];
    const float* value_W = (const float*)d_in[5];
    const float* value_b = (const float*)d_in[6];
    const float* rwse_W = (const float*)d_in[7];
    const float* rwse_b = (const float*)d_in[8];
    const float* deg_emb = (const float*)d_in[9];
    const float* W1 = (const float*)d_in[10];
    const float* b1 = (const float*)d_in[11];
    const float* W2 = (const float*)d_in[12];
    const float* b2 = (const float*)d_in[13];
    const float* gamma = (const float*)d_in[14];
    const float* beta = (const float*)d_in[15];
    const float* mean = (const float*)d_in[16];
    const float* var = (const float*)d_in[17];

    int N = in_sizes[0];
    int E = in_sizes[1] / 2;
    int RWSE = in_sizes[3] / N;
    int DEG = in_sizes[9] / DD;
    int L = in_sizes[10] / (DD * DD);

    // resolve device addresses of __device__ globals (host symbol != device ptr)
    float* d_gh = 0;
    __half* d_ghh = 0;
    cudaGetSymbolAddress((void**)&d_gh, g_h);
    cudaGetSymbolAddress((void**)&d_ghh, g_hh);

    long outRows = (long)out_size / DD;
    bool both = (outRows > (long)N);
    int G = both ? (int)(outRows - N) : (int)outRows;

    float* pooled = (float*)d_out;
    float* hout = both ? (pooled + (long)G * DD) : d_gh;

    cudaFuncSetAttribute(k_mlp2, cudaFuncAttributeMaxDynamicSharedMemorySize, SMEM_MLP2);

    // (1) degree histogram + zero(pooled,g_comb) + embedding init + weight prep
    int EB = (E + 1023) / 1024;
    int NBi = (N + 7) / 8;
    k_count_init<<<EB + NBi + 2 * L, 256>>>(edge_index, feat_id, indeg, rwse,
                                            value_W, value_b, rwse_W, rwse_b, deg_emb,
                                            W1, W2, pooled, G * DD,
                                            N, E, RWSE, DEG - 1, EB, NBi);

    // (2) single-pass rowptr scan (decoupled lookback; self-cleans g_cnt)
    int NB = (N + 511) / 512;
    k_scan<<<NB, 512>>>(N, NB);

    // (3) CSR fill (4 edges/thread)
    k_fill<<<(E + 1023) / 1024, 256>>>(edge_index, edge_index + E, E);

    // (4..) GIN layers: fp16-h gather (launch #4 = profiled) + fp16 1-term MLP
    int ntiles = (N + TM - 1) / TM;
    int lgrid = ntiles < 296 ? ntiles : 296;
    for (int l = 0; l < L; l++) {
        bool last = (l == L - 1);
        k_agg<<<(N + 7) / 8, 256>>>(N);
        k_mlp2<<<lgrid, 256, SMEM_MLP2>>>(hout, d_ghh, l,
                                          b1 + l * DD,
                                          gamma + l * DD, beta + l * DD,
                                          mean + l * DD, var + l * DD, b2 + l * DD,
                                          batch, pooled, N, last ? 1 : 0);
    }

    // final mean divide (count via binary search on sorted batch)
    k_pooldiv<<<G, 128>>>(pooled, batch, N);
}